// round 11
// baseline (speedup 1.0000x reference)
#include <cuda_runtime.h>
#include <cuda_bf16.h>
#include <cstdint>
#include <math.h>

#define NN 10000
#define NPAD 10112           // 79 * 128  (row tiles)
#define ZPAD 10240           // 80 * 128  (col tiles for 256-wide adj CTAs)
#define NE 320000
#define FIN 512
#define HIDC 256
#define ZC 64
#define NH 8
#define ND0 32
#define ND1 8
#define NEG_SLOPE 0.2f

// ---------------- scratch (static device memory; no allocations) ----------------
__device__ float g_lin0[NN * HIDC];
__device__ float g_gat0[NN * HIDC];
__device__ float g_lin1[NN * ZC];
__device__ float g_lin2[NN * ZC];
__device__ float g_mean[NN * ZC];
__device__ float g_lstd[NN * ZC];
__device__ float g_el[NN * NH];
__device__ float g_er[NN * NH];
__device__ float g_el2[NN * NH];
__device__ float g_er2[NN * NH];
__device__ float g_e[NE * NH];
__device__ int   g_deg[NN];
__device__ int   g_off[NN + 1];
__device__ int   g_cur[NN];
__device__ int   g_ssrc[NE];
__device__ __nv_bfloat16 g_zhi[ZPAD * ZC];
__device__ __nv_bfloat16 g_zlo[ZPAD * ZC];
__device__ __nv_bfloat16 g_xhi[NPAD * FIN];
__device__ __nv_bfloat16 g_xlo[NPAD * FIN];
__device__ __nv_bfloat16 g_w0thi[HIDC * FIN];
__device__ __nv_bfloat16 g_w0tlo[HIDC * FIN];

// Feature gate: tcgen05 only exists on the 'a' targets.
#if defined(__CUDA_ARCH_FEAT_SM103_ALL) || defined(__CUDA_ARCH_FEAT_SM100_ALL) || defined(__CUDA_ARCH_FEAT_SM101_ALL)
#define HAS_TCGEN05 1
#else
#define HAS_TCGEN05 0
#endif

// ---------------- PTX helpers ----------------
__device__ __forceinline__ uint32_t smem_u32(const void* p) {
    uint32_t a;
    asm("{ .reg .u64 t; cvta.to.shared.u64 t, %1; cvt.u32.u64 %0, t; }" : "=r"(a) : "l"(p));
    return a;
}
__device__ __forceinline__ uint32_t elect1() {
    uint32_t r;
    asm volatile("{ .reg .pred p; elect.sync _|p, 0xFFFFFFFF; selp.b32 %0,1,0,p; }" : "=r"(r));
    return r;
}
#define MBAR_INIT(mbar, cnt) \
    asm volatile("mbarrier.init.shared.b64 [%0], %1;" :: "r"((uint32_t)(mbar)), "r"((uint32_t)(cnt)) : "memory")
#define MBAR_INVAL(mbar) \
    asm volatile("mbarrier.inval.shared.b64 [%0];" :: "r"((uint32_t)(mbar)) : "memory")
#define MBAR_WAIT(mbar, parity) do {                                           \
    uint32_t _m = (uint32_t)(mbar), _p = (uint32_t)(parity), _d;               \
    asm volatile("{ .reg .pred p; mbarrier.try_wait.parity.acquire.cta.shared::cta.b64 p, [%1], %2; selp.b32 %0,1,0,p; }" \
                 : "=r"(_d) : "r"(_m), "r"(_p) : "memory");                    \
    if (!_d) {                                                                 \
        asm volatile("{ .reg .pred P1; WL%=: mbarrier.try_wait.parity.acquire.cta.shared::cta.b64 P1, [%0], %1, 0x989680; @P1 bra.uni WD%=; bra.uni WL%=; WD%=: }" \
                     :: "r"(_m), "r"(_p) : "memory");                          \
    }                                                                          \
} while (0)
#define FENCE_PROXY_ASYNC() asm volatile("fence.proxy.async.shared::cta;" ::: "memory")

#if HAS_TCGEN05
#define TC_ALLOC(saddr, n) \
    asm volatile("tcgen05.alloc.cta_group::1.sync.aligned.shared::cta.b32 [%0], %1;" \
                 :: "r"((uint32_t)(saddr)), "r"((uint32_t)(n)) : "memory")
#define TC_RELINQ() \
    asm volatile("tcgen05.relinquish_alloc_permit.cta_group::1.sync.aligned;")
#define TC_DEALLOC(tmem, n) \
    asm volatile("tcgen05.dealloc.cta_group::1.sync.aligned.b32 %0, %1;" :: "r"(tmem), "r"((uint32_t)(n)))
#define TC_COMMIT(mbar) \
    asm volatile("tcgen05.commit.cta_group::1.mbarrier::arrive::one.shared::cluster.b64 [%0];" \
                 :: "r"((uint32_t)(mbar)) : "memory")
#define TC_FENCE_AFTER() asm volatile("tcgen05.fence::after_thread_sync;" ::: "memory")
#define TC_FENCE_BEFORE() asm volatile("tcgen05.fence::before_thread_sync;" ::: "memory")
#define TC_WAIT_LD() asm volatile("tcgen05.wait::ld.sync.aligned;" ::: "memory")
#define TC_LD_X32(r, tmem_addr) \
    asm volatile( \
        "tcgen05.ld.sync.aligned.32x32b.x32.b32 " \
        "{%0, %1, %2, %3, %4, %5, %6, %7, " \
        " %8, %9, %10, %11, %12, %13, %14, %15, " \
        " %16, %17, %18, %19, %20, %21, %22, %23, " \
        " %24, %25, %26, %27, %28, %29, %30, %31}, [%32];" \
        : "=r"((r)[0]),  "=r"((r)[1]),  "=r"((r)[2]),  "=r"((r)[3]), \
          "=r"((r)[4]),  "=r"((r)[5]),  "=r"((r)[6]),  "=r"((r)[7]), \
          "=r"((r)[8]),  "=r"((r)[9]),  "=r"((r)[10]), "=r"((r)[11]), \
          "=r"((r)[12]), "=r"((r)[13]), "=r"((r)[14]), "=r"((r)[15]), \
          "=r"((r)[16]), "=r"((r)[17]), "=r"((r)[18]), "=r"((r)[19]), \
          "=r"((r)[20]), "=r"((r)[21]), "=r"((r)[22]), "=r"((r)[23]), \
          "=r"((r)[24]), "=r"((r)[25]), "=r"((r)[26]), "=r"((r)[27]), \
          "=r"((r)[28]), "=r"((r)[29]), "=r"((r)[30]), "=r"((r)[31]) \
        : "r"(tmem_addr))

__device__ __forceinline__ void mma_f16_ss(uint32_t d, uint64_t a, uint64_t b,
                                           uint32_t idesc, bool accum) {
    uint32_t en = accum ? 1u : 0u;
    asm volatile(
        "{\n\t"
        ".reg .pred p;\n\t"
        "setp.ne.u32 p, %5, 0;\n\t"
        "tcgen05.mma.cta_group::1.kind::f16 [%0], %1, %2, %3, {%4, %4, %4, %4}, p;\n\t"
        "}"
        :: "r"(d), "l"(a), "l"(b), "r"(idesc), "r"(0u), "r"(en)
        : "memory");
}
#endif  // HAS_TCGEN05

// SW128 SMEM descriptor (version=1, SBO=64, LBO=1)
__device__ __forceinline__ uint64_t mk_desc(uint32_t saddr) {
    const uint64_t BASE =
        (uint64_t(2) << 61) | (uint64_t(1) << 46) | (uint64_t(64) << 32) | (uint64_t(1) << 16);
    return BASE | ((uint64_t)(saddr >> 4) & 0x3FFF);
}
__device__ __forceinline__ uint32_t swz128(uint32_t off) {
    return off ^ ((off >> 3) & 0x70);
}

// ---------------- counting sort of edges by dst ----------------
__global__ void k_zero_deg() {
    int i = blockIdx.x * blockDim.x + threadIdx.x;
    if (i < NN) g_deg[i] = 0;
}

__global__ void k_hist(const int* __restrict__ dst) {
    int i = blockIdx.x * blockDim.x + threadIdx.x;
    if (i < NE) atomicAdd(&g_deg[dst[i]], 1);
}

__global__ void k_scan() {
    const int CH = 10;
    __shared__ int sh[1024];
    int t = threadIdx.x;
    int base = t * CH;
    int vals[CH];
    int loc = 0;
#pragma unroll
    for (int i = 0; i < CH; i++) {
        int idx = base + i;
        vals[i] = (idx < NN) ? g_deg[idx] : 0;
        loc += vals[i];
    }
    sh[t] = loc;
    __syncthreads();
    for (int off = 1; off < 1024; off <<= 1) {
        int v = (t >= off) ? sh[t - off] : 0;
        __syncthreads();
        sh[t] += v;
        __syncthreads();
    }
    int run = sh[t] - loc;
#pragma unroll
    for (int i = 0; i < CH; i++) {
        int idx = base + i;
        if (idx < NN) {
            g_off[idx] = run;
            g_cur[idx] = run;
            run += vals[i];
        }
    }
    if (t == 0) g_off[NN] = NE;
}

__global__ void k_scatter(const int* __restrict__ src, const int* __restrict__ dst) {
    int e = blockIdx.x * blockDim.x + threadIdx.x;
    if (e < NE) {
        int d = dst[e];
        int pos = atomicAdd(&g_cur[d], 1);
        g_ssrc[pos] = src[e];
    }
}

// ---------------- fp32 tiled GEMM (layers 1/2 only) ----------------
__global__ __launch_bounds__(256) void k_sgemm(const float* __restrict__ A,
                                               const float* __restrict__ B,
                                               float* __restrict__ C,
                                               int M, int K, int Nn) {
    __shared__ float As[64 * 32];
    __shared__ float Bs[32 * 64];
    int tid = threadIdx.x;
    int tx = tid & 15, ty = tid >> 4;
    int rowBase = blockIdx.y * 64;
    int colBase = blockIdx.x * 64;
    float acc[4][4] = {};

    for (int kb = 0; kb < K; kb += 32) {
        {
            int r = tid >> 3;
            int c = (tid & 7) << 2;
#pragma unroll
            for (int p = 0; p < 2; p++) {
                int rr = r + p * 32;
                int grow = rowBase + rr;
                float4 v = make_float4(0.f, 0.f, 0.f, 0.f);
                if (grow < M) v = *(const float4*)(A + (size_t)grow * K + kb + c);
                *(float4*)(As + rr * 32 + c) = v;
            }
            int r2 = tid >> 4;
            int c2 = (tid & 15) << 2;
#pragma unroll
            for (int p = 0; p < 2; p++) {
                int rr = r2 + p * 16;
                float4 v = *(const float4*)(B + (size_t)(kb + rr) * Nn + colBase + c2);
                *(float4*)(Bs + rr * 64 + c2) = v;
            }
        }
        __syncthreads();
#pragma unroll
        for (int kk = 0; kk < 32; kk++) {
            float4 b0 = *(const float4*)(Bs + kk * 64 + tx * 4);
            float a0 = As[(ty * 4 + 0) * 32 + kk];
            float a1 = As[(ty * 4 + 1) * 32 + kk];
            float a2 = As[(ty * 4 + 2) * 32 + kk];
            float a3 = As[(ty * 4 + 3) * 32 + kk];
            acc[0][0] += a0 * b0.x; acc[0][1] += a0 * b0.y; acc[0][2] += a0 * b0.z; acc[0][3] += a0 * b0.w;
            acc[1][0] += a1 * b0.x; acc[1][1] += a1 * b0.y; acc[1][2] += a1 * b0.z; acc[1][3] += a1 * b0.w;
            acc[2][0] += a2 * b0.x; acc[2][1] += a2 * b0.y; acc[2][2] += a2 * b0.z; acc[2][3] += a2 * b0.w;
            acc[3][0] += a3 * b0.x; acc[3][1] += a3 * b0.y; acc[3][2] += a3 * b0.z; acc[3][3] += a3 * b0.w;
        }
        __syncthreads();
    }
#pragma unroll
    for (int i = 0; i < 4; i++) {
        int grow = rowBase + ty * 4 + i;
        if (grow < M) {
            *(float4*)(C + (size_t)grow * Nn + colBase + tx * 4) =
                make_float4(acc[i][0], acc[i][1], acc[i][2], acc[i][3]);
        }
    }
}

// ---------------- feature / W0^T bf16 hi-lo splits ----------------
__global__ void k_splitx(const float* __restrict__ x) {
    int i = blockIdx.x * blockDim.x + threadIdx.x;
    if (i >= NPAD * FIN) return;
    int row = i / FIN;
    float v = (row < NN) ? x[(size_t)row * FIN + (i % FIN)] : 0.f;
    __nv_bfloat16 h = __float2bfloat16(v);
    g_xhi[i] = h;
    g_xlo[i] = __float2bfloat16(v - __bfloat162float(h));
}

__global__ void k_w0t(const float* __restrict__ W0) {
    int i = blockIdx.x * blockDim.x + threadIdx.x;
    if (i >= HIDC * FIN) return;
    int n = i / FIN, k = i % FIN;
    float v = W0[(size_t)k * HIDC + n];
    __nv_bfloat16 h = __float2bfloat16(v);
    g_w0thi[i] = h;
    g_w0tlo[i] = __float2bfloat16(v - __bfloat162float(h));
}

// ---------------- lin0 = X @ W0 via tcgen05 (bf16 hi/lo, 3 passes) ----------------
#define TC_IDESC 0x8200490u
#define L_AH 1024
#define L_AL (1024 + 16384)
#define L_BH (1024 + 2 * 16384)
#define L_BL (1024 + 4 * 16384)
#define L_SMEM (1024 + 6 * 16384)

__global__ __launch_bounds__(128)
void k_lin0_tc(float* __restrict__ out) {
#if HAS_TCGEN05
    extern __shared__ char smem[];
    uint32_t sb = smem_u32(smem);
    int tid = threadIdx.x, wid = tid >> 5, lid = tid & 31;
    int row0 = blockIdx.x * 128;

    if (wid == 0) {
        TC_ALLOC(sb + 0, 256);
        TC_RELINQ();
    }
    if (tid == 0) MBAR_INIT(sb + 8, 1);
    __syncthreads();

    uint32_t tmem;
    asm volatile("ld.shared.b32 %0, [%1];" : "=r"(tmem) : "r"(sb + 0));
    uint64_t dAh = mk_desc(sb + L_AH);
    uint64_t dAl = mk_desc(sb + L_AL);
    int ph = 0;

    for (int kb = 0; kb < 8; kb++) {
        int k0 = kb * 64;
#pragma unroll
        for (int it = 0; it < 8; it++) {
            int idx = it * 128 + tid;
            int r = idx >> 3;
            int c = idx & 7;
            uint32_t sw = swz128((uint32_t)(r * 128 + c * 16));
            *(uint4*)(smem + L_AH + sw) =
                *((const uint4*)(g_xhi + (size_t)(row0 + r) * FIN + k0) + c);
            *(uint4*)(smem + L_AL + sw) =
                *((const uint4*)(g_xlo + (size_t)(row0 + r) * FIN + k0) + c);
        }
#pragma unroll
        for (int it = 0; it < 16; it++) {
            int idx = it * 128 + tid;
            int j = idx >> 10;
            int rem = idx & 1023;
            int rr = rem >> 3;
            int c = rem & 7;
            uint32_t sw = swz128((uint32_t)(rr * 128 + c * 16)) + j * 16384;
            *(uint4*)(smem + L_BH + sw) =
                *((const uint4*)(g_w0thi + (size_t)(j * 128 + rr) * FIN + k0) + c);
            *(uint4*)(smem + L_BL + sw) =
                *((const uint4*)(g_w0tlo + (size_t)(j * 128 + rr) * FIN + k0) + c);
        }
        FENCE_PROXY_ASYNC();
        __syncthreads();

        if (wid == 0 && elect1()) {
#pragma unroll
            for (int j = 0; j < 2; j++) {
                uint64_t dBh = mk_desc(sb + L_BH + j * 16384);
                uint64_t dBl = mk_desc(sb + L_BL + j * 16384);
                uint32_t dacc = tmem + j * 128;
#pragma unroll
                for (int p = 0; p < 3; p++) {
                    uint64_t da = (p == 2) ? dAl : dAh;
                    uint64_t db = (p == 1) ? dBl : dBh;
#pragma unroll
                    for (int k = 0; k < 4; k++) {
                        bool first = (kb == 0) && (p == 0) && (k == 0);
                        mma_f16_ss(dacc, da + k * 2, db + k * 2, TC_IDESC, !first);
                    }
                }
            }
            TC_COMMIT(sb + 8);
        }
        MBAR_WAIT(sb + 8, ph & 1);
        ph++;
        __syncthreads();
    }

    TC_FENCE_AFTER();
    int r = row0 + wid * 32 + lid;
#pragma unroll
    for (int j = 0; j < 2; j++) {
#pragma unroll
        for (int ch = 0; ch < 4; ch++) {
            uint32_t dr[32];
            TC_LD_X32(dr, tmem + j * 128 + ch * 32);
            TC_WAIT_LD();
            if (r < NN) {
                float* orow = out + (size_t)r * HIDC + j * 128 + ch * 32;
#pragma unroll
                for (int q = 0; q < 8; q++)
                    *(float4*)(orow + q * 4) = make_float4(
                        __uint_as_float(dr[q * 4]), __uint_as_float(dr[q * 4 + 1]),
                        __uint_as_float(dr[q * 4 + 2]), __uint_as_float(dr[q * 4 + 3]));
            }
        }
    }
    TC_FENCE_BEFORE();
    __syncthreads();
    if (tid == 0) MBAR_INVAL(sb + 8);
    __syncthreads();
    if (wid == 0) TC_DEALLOC(tmem, 256);
#endif  // HAS_TCGEN05
}

// ---------------- el/er ----------------
template <int D>
__global__ void k_elr(const float* __restrict__ lin,
                      const float* __restrict__ al,
                      const float* __restrict__ ar,
                      float* __restrict__ elo, float* __restrict__ ero) {
    int i = blockIdx.x * blockDim.x + threadIdx.x;
    if (i >= NN * NH) return;
    int n = i / NH, h = i % NH;
    float el = 0.f, er = 0.f;
#pragma unroll
    for (int d = 0; d < D; d++) {
        float v = lin[n * (NH * D) + h * D + d];
        el += v * al[h * D + d];
        er += v * ar[h * D + d];
    }
    elo[i] = el;
    ero[i] = er;
}

// ---------------- fused per-node GAT ----------------
template <int D, bool RELU>
__global__ void k_gat_fused(const float* __restrict__ lin,
                            const float* __restrict__ elp,
                            const float* __restrict__ erp,
                            const float* __restrict__ bias,
                            float* __restrict__ out) {
    const int C = NH * D;
    int n = blockIdx.x;
    int tid = threadIdx.x;
    int beg = g_off[n], end = g_off[n + 1];
    __shared__ int   s_m[NH];
    __shared__ float s_sum[NH];
    __shared__ int   s_src[32];
    __shared__ float s_ex[32 * NH];
    if (tid < NH) { s_m[tid] = __float_as_int(-INFINITY); s_sum[tid] = 0.f; }
    __syncthreads();

    {
        int h = tid & 7;
        float ern = erp[n * NH + h];
        for (int j0 = beg + (tid >> 3); j0 < end; j0 += C / NH) {
            int s = g_ssrc[j0];
            float v = elp[s * NH + h] + ern;
            v = (v > 0.f) ? v : NEG_SLOPE * v;
            g_e[(size_t)j0 * NH + h] = v;
            if (v >= 0.f)
                atomicMax(&s_m[h], __float_as_int(v));
            else
                atomicMin((unsigned int*)&s_m[h], (unsigned int)__float_as_int(v));
        }
    }
    __syncthreads();

    float acc = 0.f;
    int hA = tid / D;
    for (int base = beg; base < end; base += 32) {
        int cnt = min(32, end - base);
        __syncthreads();
        if (tid < cnt) s_src[tid] = g_ssrc[base + tid];
        for (int i = tid; i < cnt * NH; i += C) {
            float ex = __expf(g_e[(size_t)base * NH + i] - __int_as_float(s_m[i & 7]));
            s_ex[i] = ex;
            atomicAdd(&s_sum[i & 7], ex);
        }
        __syncthreads();
        for (int jj = 0; jj < cnt; jj++)
            acc += lin[(size_t)s_src[jj] * C + tid] * s_ex[jj * NH + hA];
    }
    float v = (end > beg) ? acc / s_sum[hA] : 0.f;
    v += bias[tid];
    if (RELU) v = fmaxf(v, 0.f);
    out[(size_t)n * C + tid] = v;
}

// ---------------- z = mean + noise*exp(log_std); fused bf16 hi/lo split ----------------
__global__ void k_z_split(const float* __restrict__ noise, float* __restrict__ zout) {
    int i = blockIdx.x * blockDim.x + threadIdx.x;
    if (i >= ZPAD * ZC) return;
    float v = 0.f;
    if (i < NN * ZC) {
        v = g_mean[i] + noise[i] * expf(g_lstd[i]);
        zout[i] = v;
    }
    __nv_bfloat16 h = __float2bfloat16(v);
    g_zhi[i] = h;
    g_zlo[i] = __float2bfloat16(v - __bfloat162float(h));
}

// ---------------- adj = sigmoid(z @ z^T) via tcgen05, 128x256 per CTA ----------------
#define A4_AH 1024
#define A4_AL (1024 + 16384)
#define A4_B  (1024 + 2 * 16384)   // 4 tiles: Bh0, Bl0, Bh1, Bl1
#define A4_SMEM (1024 + 6 * 16384)

__global__ __launch_bounds__(128)
void k_adj_tc4(float* __restrict__ adj) {
#if HAS_TCGEN05
    extern __shared__ char smem[];
    uint32_t sb = smem_u32(smem);
    int tid = threadIdx.x, wid = tid >> 5, lid = tid & 31;
    int row0 = blockIdx.y * 128;
    int colBase = blockIdx.x * 256;

    if (wid == 0) {
        TC_ALLOC(sb + 0, 256);
        TC_RELINQ();
    }
    if (tid == 0) MBAR_INIT(sb + 8, 1);

    // A tiles (Ah, Al) + B tiles for 2 column tiles (Bh0, Bl0, Bh1, Bl1)
#pragma unroll
    for (int it = 0; it < 8; it++) {
        int idx = it * 128 + tid;
        int r = idx >> 3;
        int c = idx & 7;
        uint32_t sw = swz128((uint32_t)(r * 128 + c * 16));
        *(uint4*)(smem + A4_AH + sw) = *((const uint4*)(g_zhi + (size_t)(row0 + r) * ZC) + c);
        *(uint4*)(smem + A4_AL + sw) = *((const uint4*)(g_zlo + (size_t)(row0 + r) * ZC) + c);
#pragma unroll
        for (int j = 0; j < 2; j++) {
            int cr = colBase + j * 128 + r;
            *(uint4*)(smem + A4_B + j * 32768 + sw) =
                *((const uint4*)(g_zhi + (size_t)cr * ZC) + c);
            *(uint4*)(smem + A4_B + j * 32768 + 16384 + sw) =
                *((const uint4*)(g_zlo + (size_t)cr * ZC) + c);
        }
    }
    FENCE_PROXY_ASYNC();
    __syncthreads();

    uint32_t tmem;
    asm volatile("ld.shared.b32 %0, [%1];" : "=r"(tmem) : "r"(sb + 0));

    if (wid == 0 && elect1()) {
        uint64_t dAh = mk_desc(sb + A4_AH);
        uint64_t dAl = mk_desc(sb + A4_AL);
#pragma unroll
        for (int j = 0; j < 2; j++) {
            uint64_t dBh = mk_desc(sb + A4_B + j * 32768);
            uint64_t dBl = mk_desc(sb + A4_B + j * 32768 + 16384);
            uint32_t dacc = tmem + j * 128;
#pragma unroll
            for (int p = 0; p < 3; p++) {
                uint64_t da = (p == 2) ? dAl : dAh;
                uint64_t db = (p == 1) ? dBl : dBh;
#pragma unroll
                for (int k = 0; k < 4; k++) {
                    bool first = (p == 0) && (k == 0);
                    mma_f16_ss(dacc, da + k * 2, db + k * 2, TC_IDESC, !first);
                }
            }
        }
        TC_COMMIT(sb + 8);
    }

    MBAR_WAIT(sb + 8, 0);
    TC_FENCE_AFTER();

    int r = row0 + wid * 32 + lid;
#pragma unroll
    for (int j = 0; j < 2; j++) {
        // batched LDTM: 4 loads, one wait
        uint32_t dr[128];
#pragma unroll
        for (int ch = 0; ch < 4; ch++)
            TC_LD_X32(dr + ch * 32, tmem + j * 128 + ch * 32);
        TC_WAIT_LD();
        if (r < NN) {
            int c0 = colBase + j * 128;
            float* orow = adj + (size_t)r * NN + c0;
            if (c0 + 127 < NN) {
#pragma unroll
                for (int q = 0; q < 32; q++) {
                    float v0 = 1.f / (1.f + __expf(-__uint_as_float(dr[q * 4])));
                    float v1 = 1.f / (1.f + __expf(-__uint_as_float(dr[q * 4 + 1])));
                    float v2 = 1.f / (1.f + __expf(-__uint_as_float(dr[q * 4 + 2])));
                    float v3 = 1.f / (1.f + __expf(-__uint_as_float(dr[q * 4 + 3])));
                    *(float4*)(orow + q * 4) = make_float4(v0, v1, v2, v3);
                }
            } else {
#pragma unroll
                for (int q = 0; q < 128; q++) {
                    if (c0 + q < NN)
                        orow[q] = 1.f / (1.f + __expf(-__uint_as_float(dr[q])));
                }
            }
        }
    }
    TC_FENCE_BEFORE();
    __syncthreads();
    if (tid == 0) MBAR_INVAL(sb + 8);
    __syncthreads();
    if (wid == 0) TC_DEALLOC(tmem, 256);
#endif  // HAS_TCGEN05
}

// ---------------- launcher ----------------
extern "C" void kernel_launch(void* const* d_in, const int* in_sizes, int n_in,
                              void* d_out, int out_size) {
    const float* features = (const float*)d_in[0];
    const int*   src      = (const int*)d_in[1];
    const int*   dst      = (const int*)d_in[2];
    const float* noise    = (const float*)d_in[3];
    const float* W0  = (const float*)d_in[4];
    const float* al0 = (const float*)d_in[5];
    const float* ar0 = (const float*)d_in[6];
    const float* b0  = (const float*)d_in[7];
    const float* W1  = (const float*)d_in[8];
    const float* al1 = (const float*)d_in[9];
    const float* ar1 = (const float*)d_in[10];
    const float* b1  = (const float*)d_in[11];
    const float* W2  = (const float*)d_in[12];
    const float* al2 = (const float*)d_in[13];
    const float* ar2 = (const float*)d_in[14];
    const float* b2  = (const float*)d_in[15];

    float* out = (float*)d_out;
    float* z_out = out;
    float* adj_out = out + (size_t)NN * ZC;

    void* p;
    cudaGetSymbolAddress(&p, g_lin0); float* lin0 = (float*)p;
    cudaGetSymbolAddress(&p, g_gat0); float* gat0 = (float*)p;
    cudaGetSymbolAddress(&p, g_lin1); float* lin1 = (float*)p;
    cudaGetSymbolAddress(&p, g_lin2); float* lin2 = (float*)p;
    cudaGetSymbolAddress(&p, g_mean); float* meanp = (float*)p;
    cudaGetSymbolAddress(&p, g_lstd); float* lstdp = (float*)p;
    cudaGetSymbolAddress(&p, g_el);  float* el = (float*)p;
    cudaGetSymbolAddress(&p, g_er);  float* er = (float*)p;
    cudaGetSymbolAddress(&p, g_el2); float* el2 = (float*)p;
    cudaGetSymbolAddress(&p, g_er2); float* er2 = (float*)p;

    // edge sort by dst (shared by all 3 GAT layers)
    k_zero_deg<<<(NN + 255) / 256, 256>>>();
    k_hist<<<(NE + 255) / 256, 256>>>(dst);
    k_scan<<<1, 1024>>>();
    k_scatter<<<(NE + 255) / 256, 256>>>(src, dst);

    const int ngrid = (NN * NH + 255) / 256;

    // ---- layer 0: 512 -> 256, relu (tcgen05 GEMM) ----
    k_splitx<<<(NPAD * FIN + 255) / 256, 256>>>(features);
    k_w0t<<<(HIDC * FIN + 255) / 256, 256>>>(W0);
    cudaFuncSetAttribute(k_lin0_tc, cudaFuncAttributeMaxDynamicSharedMemorySize, L_SMEM);
    k_lin0_tc<<<NPAD / 128, 128, L_SMEM>>>(lin0);
    k_elr<ND0><<<ngrid, 256>>>(lin0, al0, ar0, el, er);
    k_gat_fused<ND0, true><<<NN, HIDC>>>(lin0, el, er, b0, gat0);

    // ---- layers 1 & 2: 256 -> 64 ----
    k_sgemm<<<dim3(ZC / 64, (NN + 63) / 64), 256>>>(gat0, W1, lin1, NN, HIDC, ZC);
    k_sgemm<<<dim3(ZC / 64, (NN + 63) / 64), 256>>>(gat0, W2, lin2, NN, HIDC, ZC);
    k_elr<ND1><<<ngrid, 256>>>(lin1, al1, ar1, el, er);
    k_elr<ND1><<<ngrid, 256>>>(lin2, al2, ar2, el2, er2);
    k_gat_fused<ND1, false><<<NN, ZC>>>(lin1, el, er, b1, meanp);
    k_gat_fused<ND1, false><<<NN, ZC>>>(lin2, el2, er2, b2, lstdp);

    // ---- z + bf16 hi/lo split (fused, padded to ZPAD) ----
    k_z_split<<<(ZPAD * ZC + 255) / 256, 256>>>(noise, z_out);

    // ---- adj = sigmoid(z @ z^T) via tcgen05, 128x256 tiles ----
    cudaFuncSetAttribute(k_adj_tc4, cudaFuncAttributeMaxDynamicSharedMemorySize, A4_SMEM);
    k_adj_tc4<<<dim3(ZPAD / 256, NPAD / 128), 128, A4_SMEM>>>(adj_out);
}

// round 12
// speedup vs baseline: 1.0735x; 1.0735x over previous
#include <cuda_runtime.h>
#include <cuda_bf16.h>
#include <cstdint>
#include <math.h>

#define NN 10000
#define NPAD 10112           // 79 * 128
#define NE 320000
#define FIN 512
#define HIDC 256
#define ZC 64
#define NH 8
#define ND0 32
#define ND1 8
#define NEG_SLOPE 0.2f

// ---------------- scratch (static device memory; no allocations) ----------------
__device__ float g_lin0[NN * HIDC];
__device__ float g_gat0[NN * HIDC];
__device__ float g_lin1[NN * ZC];
__device__ float g_lin2[NN * ZC];
__device__ float g_mean[NN * ZC];
__device__ float g_lstd[NN * ZC];
__device__ float g_el[NN * NH];
__device__ float g_er[NN * NH];
__device__ float g_el2[NN * NH];
__device__ float g_er2[NN * NH];
__device__ float g_e[NE * NH];
__device__ int   g_deg[NN];
__device__ int   g_off[NN + 1];
__device__ int   g_cur[NN];
__device__ int   g_ssrc[NE];
__device__ __nv_bfloat16 g_zhi[NPAD * ZC];
__device__ __nv_bfloat16 g_zlo[NPAD * ZC];
__device__ __nv_bfloat16 g_xhi[NPAD * FIN];
__device__ __nv_bfloat16 g_xlo[NPAD * FIN];
__device__ __nv_bfloat16 g_w0thi[HIDC * FIN];
__device__ __nv_bfloat16 g_w0tlo[HIDC * FIN];

// Feature gate: tcgen05 only exists on the 'a' targets.
#if defined(__CUDA_ARCH_FEAT_SM103_ALL) || defined(__CUDA_ARCH_FEAT_SM100_ALL) || defined(__CUDA_ARCH_FEAT_SM101_ALL)
#define HAS_TCGEN05 1
#else
#define HAS_TCGEN05 0
#endif

// ---------------- PTX helpers ----------------
__device__ __forceinline__ uint32_t smem_u32(const void* p) {
    uint32_t a;
    asm("{ .reg .u64 t; cvta.to.shared.u64 t, %1; cvt.u32.u64 %0, t; }" : "=r"(a) : "l"(p));
    return a;
}
__device__ __forceinline__ uint32_t elect1() {
    uint32_t r;
    asm volatile("{ .reg .pred p; elect.sync _|p, 0xFFFFFFFF; selp.b32 %0,1,0,p; }" : "=r"(r));
    return r;
}
#define MBAR_INIT(mbar, cnt) \
    asm volatile("mbarrier.init.shared.b64 [%0], %1;" :: "r"((uint32_t)(mbar)), "r"((uint32_t)(cnt)) : "memory")
#define MBAR_INVAL(mbar) \
    asm volatile("mbarrier.inval.shared.b64 [%0];" :: "r"((uint32_t)(mbar)) : "memory")
#define MBAR_WAIT(mbar, parity) do {                                           \
    uint32_t _m = (uint32_t)(mbar), _p = (uint32_t)(parity), _d;               \
    asm volatile("{ .reg .pred p; mbarrier.try_wait.parity.acquire.cta.shared::cta.b64 p, [%1], %2; selp.b32 %0,1,0,p; }" \
                 : "=r"(_d) : "r"(_m), "r"(_p) : "memory");                    \
    if (!_d) {                                                                 \
        asm volatile("{ .reg .pred P1; WL%=: mbarrier.try_wait.parity.acquire.cta.shared::cta.b64 P1, [%0], %1, 0x989680; @P1 bra.uni WD%=; bra.uni WL%=; WD%=: }" \
                     :: "r"(_m), "r"(_p) : "memory");                          \
    }                                                                          \
} while (0)
#define FENCE_PROXY_ASYNC() asm volatile("fence.proxy.async.shared::cta;" ::: "memory")

#if HAS_TCGEN05
#define TC_ALLOC(saddr, n) \
    asm volatile("tcgen05.alloc.cta_group::1.sync.aligned.shared::cta.b32 [%0], %1;" \
                 :: "r"((uint32_t)(saddr)), "r"((uint32_t)(n)) : "memory")
#define TC_RELINQ() \
    asm volatile("tcgen05.relinquish_alloc_permit.cta_group::1.sync.aligned;")
#define TC_DEALLOC(tmem, n) \
    asm volatile("tcgen05.dealloc.cta_group::1.sync.aligned.b32 %0, %1;" :: "r"(tmem), "r"((uint32_t)(n)))
#define TC_COMMIT(mbar) \
    asm volatile("tcgen05.commit.cta_group::1.mbarrier::arrive::one.shared::cluster.b64 [%0];" \
                 :: "r"((uint32_t)(mbar)) : "memory")
#define TC_FENCE_AFTER() asm volatile("tcgen05.fence::after_thread_sync;" ::: "memory")
#define TC_FENCE_BEFORE() asm volatile("tcgen05.fence::before_thread_sync;" ::: "memory")
#define TC_WAIT_LD() asm volatile("tcgen05.wait::ld.sync.aligned;" ::: "memory")
#define TC_LD_X32(r, tmem_addr) \
    asm volatile( \
        "tcgen05.ld.sync.aligned.32x32b.x32.b32 " \
        "{%0, %1, %2, %3, %4, %5, %6, %7, " \
        " %8, %9, %10, %11, %12, %13, %14, %15, " \
        " %16, %17, %18, %19, %20, %21, %22, %23, " \
        " %24, %25, %26, %27, %28, %29, %30, %31}, [%32];" \
        : "=r"((r)[0]),  "=r"((r)[1]),  "=r"((r)[2]),  "=r"((r)[3]), \
          "=r"((r)[4]),  "=r"((r)[5]),  "=r"((r)[6]),  "=r"((r)[7]), \
          "=r"((r)[8]),  "=r"((r)[9]),  "=r"((r)[10]), "=r"((r)[11]), \
          "=r"((r)[12]), "=r"((r)[13]), "=r"((r)[14]), "=r"((r)[15]), \
          "=r"((r)[16]), "=r"((r)[17]), "=r"((r)[18]), "=r"((r)[19]), \
          "=r"((r)[20]), "=r"((r)[21]), "=r"((r)[22]), "=r"((r)[23]), \
          "=r"((r)[24]), "=r"((r)[25]), "=r"((r)[26]), "=r"((r)[27]), \
          "=r"((r)[28]), "=r"((r)[29]), "=r"((r)[30]), "=r"((r)[31]) \
        : "r"(tmem_addr))

__device__ __forceinline__ void mma_f16_ss(uint32_t d, uint64_t a, uint64_t b,
                                           uint32_t idesc, bool accum) {
    uint32_t en = accum ? 1u : 0u;
    asm volatile(
        "{\n\t"
        ".reg .pred p;\n\t"
        "setp.ne.u32 p, %5, 0;\n\t"
        "tcgen05.mma.cta_group::1.kind::f16 [%0], %1, %2, %3, {%4, %4, %4, %4}, p;\n\t"
        "}"
        :: "r"(d), "l"(a), "l"(b), "r"(idesc), "r"(0u), "r"(en)
        : "memory");
}
#endif  // HAS_TCGEN05

// SW128 SMEM descriptor (version=1, SBO=64, LBO=1)
__device__ __forceinline__ uint64_t mk_desc(uint32_t saddr) {
    const uint64_t BASE =
        (uint64_t(2) << 61) | (uint64_t(1) << 46) | (uint64_t(64) << 32) | (uint64_t(1) << 16);
    return BASE | ((uint64_t)(saddr >> 4) & 0x3FFF);
}
__device__ __forceinline__ uint32_t swz128(uint32_t off) {
    return off ^ ((off >> 3) & 0x70);
}

// ---------------- counting sort of edges by dst ----------------
__global__ void k_zero_deg() {
    int i = blockIdx.x * blockDim.x + threadIdx.x;
    if (i < NN) g_deg[i] = 0;
}

__global__ void k_hist(const int* __restrict__ dst) {
    int i = blockIdx.x * blockDim.x + threadIdx.x;
    if (i < NE) atomicAdd(&g_deg[dst[i]], 1);
}

__global__ void k_scan() {
    const int CH = 10;
    __shared__ int sh[1024];
    int t = threadIdx.x;
    int base = t * CH;
    int vals[CH];
    int loc = 0;
#pragma unroll
    for (int i = 0; i < CH; i++) {
        int idx = base + i;
        vals[i] = (idx < NN) ? g_deg[idx] : 0;
        loc += vals[i];
    }
    sh[t] = loc;
    __syncthreads();
    for (int off = 1; off < 1024; off <<= 1) {
        int v = (t >= off) ? sh[t - off] : 0;
        __syncthreads();
        sh[t] += v;
        __syncthreads();
    }
    int run = sh[t] - loc;
#pragma unroll
    for (int i = 0; i < CH; i++) {
        int idx = base + i;
        if (idx < NN) {
            g_off[idx] = run;
            g_cur[idx] = run;
            run += vals[i];
        }
    }
    if (t == 0) g_off[NN] = NE;
}

__global__ void k_scatter(const int* __restrict__ src, const int* __restrict__ dst) {
    int e = blockIdx.x * blockDim.x + threadIdx.x;
    if (e < NE) {
        int d = dst[e];
        int pos = atomicAdd(&g_cur[d], 1);
        g_ssrc[pos] = src[e];
    }
}

// ---------------- fp32 tiled GEMM, dual-output (layers 1/2 in one launch) ----------------
__global__ __launch_bounds__(256) void k_sgemm2(const float* __restrict__ A,
                                                const float* __restrict__ B1,
                                                const float* __restrict__ B2,
                                                float* __restrict__ C1,
                                                float* __restrict__ C2,
                                                int M, int K, int Nn) {
    const float* B = (blockIdx.z == 0) ? B1 : B2;
    float* C = (blockIdx.z == 0) ? C1 : C2;
    __shared__ float As[64 * 32];
    __shared__ float Bs[32 * 64];
    int tid = threadIdx.x;
    int tx = tid & 15, ty = tid >> 4;
    int rowBase = blockIdx.y * 64;
    int colBase = blockIdx.x * 64;
    float acc[4][4] = {};

    for (int kb = 0; kb < K; kb += 32) {
        {
            int r = tid >> 3;
            int c = (tid & 7) << 2;
#pragma unroll
            for (int p = 0; p < 2; p++) {
                int rr = r + p * 32;
                int grow = rowBase + rr;
                float4 v = make_float4(0.f, 0.f, 0.f, 0.f);
                if (grow < M) v = *(const float4*)(A + (size_t)grow * K + kb + c);
                *(float4*)(As + rr * 32 + c) = v;
            }
            int r2 = tid >> 4;
            int c2 = (tid & 15) << 2;
#pragma unroll
            for (int p = 0; p < 2; p++) {
                int rr = r2 + p * 16;
                float4 v = *(const float4*)(B + (size_t)(kb + rr) * Nn + colBase + c2);
                *(float4*)(Bs + rr * 64 + c2) = v;
            }
        }
        __syncthreads();
#pragma unroll
        for (int kk = 0; kk < 32; kk++) {
            float4 b0 = *(const float4*)(Bs + kk * 64 + tx * 4);
            float a0 = As[(ty * 4 + 0) * 32 + kk];
            float a1 = As[(ty * 4 + 1) * 32 + kk];
            float a2 = As[(ty * 4 + 2) * 32 + kk];
            float a3 = As[(ty * 4 + 3) * 32 + kk];
            acc[0][0] += a0 * b0.x; acc[0][1] += a0 * b0.y; acc[0][2] += a0 * b0.z; acc[0][3] += a0 * b0.w;
            acc[1][0] += a1 * b0.x; acc[1][1] += a1 * b0.y; acc[1][2] += a1 * b0.z; acc[1][3] += a1 * b0.w;
            acc[2][0] += a2 * b0.x; acc[2][1] += a2 * b0.y; acc[2][2] += a2 * b0.z; acc[2][3] += a2 * b0.w;
            acc[3][0] += a3 * b0.x; acc[3][1] += a3 * b0.y; acc[3][2] += a3 * b0.z; acc[3][3] += a3 * b0.w;
        }
        __syncthreads();
    }
#pragma unroll
    for (int i = 0; i < 4; i++) {
        int grow = rowBase + ty * 4 + i;
        if (grow < M) {
            *(float4*)(C + (size_t)grow * Nn + colBase + tx * 4) =
                make_float4(acc[i][0], acc[i][1], acc[i][2], acc[i][3]);
        }
    }
}

// ---------------- feature / W0^T bf16 hi-lo splits ----------------
__global__ void k_splitx(const float* __restrict__ x) {
    int i = blockIdx.x * blockDim.x + threadIdx.x;
    if (i >= NPAD * FIN) return;
    int row = i / FIN;
    float v = (row < NN) ? x[(size_t)row * FIN + (i % FIN)] : 0.f;
    __nv_bfloat16 h = __float2bfloat16(v);
    g_xhi[i] = h;
    g_xlo[i] = __float2bfloat16(v - __bfloat162float(h));
}

__global__ void k_w0t(const float* __restrict__ W0) {
    int i = blockIdx.x * blockDim.x + threadIdx.x;
    if (i >= HIDC * FIN) return;
    int n = i / FIN, k = i % FIN;
    float v = W0[(size_t)k * HIDC + n];
    __nv_bfloat16 h = __float2bfloat16(v);
    g_w0thi[i] = h;
    g_w0tlo[i] = __float2bfloat16(v - __bfloat162float(h));
}

// ---------------- lin0 = X @ W0 via tcgen05 (bf16 hi/lo, 3 passes) ----------------
#define TC_IDESC 0x8200490u
#define L_AH 1024
#define L_AL (1024 + 16384)
#define L_BH (1024 + 2 * 16384)
#define L_BL (1024 + 4 * 16384)
#define L_SMEM (1024 + 6 * 16384)

__global__ __launch_bounds__(128)
void k_lin0_tc(float* __restrict__ out) {
#if HAS_TCGEN05
    extern __shared__ char smem[];
    uint32_t sb = smem_u32(smem);
    int tid = threadIdx.x, wid = tid >> 5, lid = tid & 31;
    int row0 = blockIdx.x * 128;

    if (wid == 0) {
        TC_ALLOC(sb + 0, 256);
        TC_RELINQ();
    }
    if (tid == 0) MBAR_INIT(sb + 8, 1);
    __syncthreads();

    uint32_t tmem;
    asm volatile("ld.shared.b32 %0, [%1];" : "=r"(tmem) : "r"(sb + 0));
    uint64_t dAh = mk_desc(sb + L_AH);
    uint64_t dAl = mk_desc(sb + L_AL);
    int ph = 0;

    for (int kb = 0; kb < 8; kb++) {
        int k0 = kb * 64;
#pragma unroll
        for (int it = 0; it < 8; it++) {
            int idx = it * 128 + tid;
            int r = idx >> 3;
            int c = idx & 7;
            uint32_t sw = swz128((uint32_t)(r * 128 + c * 16));
            *(uint4*)(smem + L_AH + sw) =
                *((const uint4*)(g_xhi + (size_t)(row0 + r) * FIN + k0) + c);
            *(uint4*)(smem + L_AL + sw) =
                *((const uint4*)(g_xlo + (size_t)(row0 + r) * FIN + k0) + c);
        }
#pragma unroll
        for (int it = 0; it < 16; it++) {
            int idx = it * 128 + tid;
            int j = idx >> 10;
            int rem = idx & 1023;
            int rr = rem >> 3;
            int c = rem & 7;
            uint32_t sw = swz128((uint32_t)(rr * 128 + c * 16)) + j * 16384;
            *(uint4*)(smem + L_BH + sw) =
                *((const uint4*)(g_w0thi + (size_t)(j * 128 + rr) * FIN + k0) + c);
            *(uint4*)(smem + L_BL + sw) =
                *((const uint4*)(g_w0tlo + (size_t)(j * 128 + rr) * FIN + k0) + c);
        }
        FENCE_PROXY_ASYNC();
        __syncthreads();

        if (wid == 0 && elect1()) {
#pragma unroll
            for (int j = 0; j < 2; j++) {
                uint64_t dBh = mk_desc(sb + L_BH + j * 16384);
                uint64_t dBl = mk_desc(sb + L_BL + j * 16384);
                uint32_t dacc = tmem + j * 128;
#pragma unroll
                for (int p = 0; p < 3; p++) {
                    uint64_t da = (p == 2) ? dAl : dAh;
                    uint64_t db = (p == 1) ? dBl : dBh;
#pragma unroll
                    for (int k = 0; k < 4; k++) {
                        bool first = (kb == 0) && (p == 0) && (k == 0);
                        mma_f16_ss(dacc, da + k * 2, db + k * 2, TC_IDESC, !first);
                    }
                }
            }
            TC_COMMIT(sb + 8);
        }
        MBAR_WAIT(sb + 8, ph & 1);
        ph++;
        __syncthreads();
    }

    TC_FENCE_AFTER();
    int r = row0 + wid * 32 + lid;
#pragma unroll
    for (int j = 0; j < 2; j++) {
#pragma unroll
        for (int hp = 0; hp < 2; hp++) {
            uint32_t dr[64];
            TC_LD_X32(dr, tmem + j * 128 + hp * 64);
            TC_LD_X32(dr + 32, tmem + j * 128 + hp * 64 + 32);
            TC_WAIT_LD();
            if (r < NN) {
                float* orow = out + (size_t)r * HIDC + j * 128 + hp * 64;
#pragma unroll
                for (int q = 0; q < 16; q++)
                    *(float4*)(orow + q * 4) = make_float4(
                        __uint_as_float(dr[q * 4]), __uint_as_float(dr[q * 4 + 1]),
                        __uint_as_float(dr[q * 4 + 2]), __uint_as_float(dr[q * 4 + 3]));
            }
        }
    }
    TC_FENCE_BEFORE();
    __syncthreads();
    if (tid == 0) MBAR_INVAL(sb + 8);
    __syncthreads();
    if (wid == 0) TC_DEALLOC(tmem, 256);
#endif  // HAS_TCGEN05
}

// ---------------- el/er ----------------
template <int D>
__global__ void k_elr(const float* __restrict__ lin,
                      const float* __restrict__ al,
                      const float* __restrict__ ar,
                      float* __restrict__ elo, float* __restrict__ ero) {
    int i = blockIdx.x * blockDim.x + threadIdx.x;
    if (i >= NN * NH) return;
    int n = i / NH, h = i % NH;
    float el = 0.f, er = 0.f;
#pragma unroll
    for (int d = 0; d < D; d++) {
        float v = lin[n * (NH * D) + h * D + d];
        el += v * al[h * D + d];
        er += v * ar[h * D + d];
    }
    elo[i] = el;
    ero[i] = er;
}

// ---------------- fused per-node GAT ----------------
template <int D, bool RELU>
__global__ void k_gat_fused(const float* __restrict__ lin,
                            const float* __restrict__ elp,
                            const float* __restrict__ erp,
                            const float* __restrict__ bias,
                            float* __restrict__ out) {
    const int C = NH * D;
    int n = blockIdx.x;
    int tid = threadIdx.x;
    int beg = g_off[n], end = g_off[n + 1];
    __shared__ int   s_m[NH];
    __shared__ float s_sum[NH];
    __shared__ int   s_src[32];
    __shared__ float s_ex[32 * NH];
    if (tid < NH) { s_m[tid] = __float_as_int(-INFINITY); s_sum[tid] = 0.f; }
    __syncthreads();

    {
        int h = tid & 7;
        float ern = erp[n * NH + h];
        for (int j0 = beg + (tid >> 3); j0 < end; j0 += C / NH) {
            int s = g_ssrc[j0];
            float v = elp[s * NH + h] + ern;
            v = (v > 0.f) ? v : NEG_SLOPE * v;
            g_e[(size_t)j0 * NH + h] = v;
            if (v >= 0.f)
                atomicMax(&s_m[h], __float_as_int(v));
            else
                atomicMin((unsigned int*)&s_m[h], (unsigned int)__float_as_int(v));
        }
    }
    __syncthreads();

    float acc = 0.f;
    int hA = tid / D;
    for (int base = beg; base < end; base += 32) {
        int cnt = min(32, end - base);
        __syncthreads();
        if (tid < cnt) s_src[tid] = g_ssrc[base + tid];
        for (int i = tid; i < cnt * NH; i += C) {
            float ex = __expf(g_e[(size_t)base * NH + i] - __int_as_float(s_m[i & 7]));
            s_ex[i] = ex;
            atomicAdd(&s_sum[i & 7], ex);
        }
        __syncthreads();
        for (int jj = 0; jj < cnt; jj++)
            acc += lin[(size_t)s_src[jj] * C + tid] * s_ex[jj * NH + hA];
    }
    float v = (end > beg) ? acc / s_sum[hA] : 0.f;
    v += bias[tid];
    if (RELU) v = fmaxf(v, 0.f);
    out[(size_t)n * C + tid] = v;
}

// ---------------- z = mean + noise*exp(log_std); fused bf16 hi/lo split ----------------
__global__ void k_z_split(const float* __restrict__ noise, float* __restrict__ zout) {
    int i = blockIdx.x * blockDim.x + threadIdx.x;
    if (i >= NPAD * ZC) return;
    float v = 0.f;
    if (i < NN * ZC) {
        v = g_mean[i] + noise[i] * expf(g_lstd[i]);
        zout[i] = v;
    }
    __nv_bfloat16 h = __float2bfloat16(v);
    g_zhi[i] = h;
    g_zlo[i] = __float2bfloat16(v - __bfloat162float(h));
}

// ---------------- adj = sigmoid(z @ z^T) via tcgen05 (round-10 config, paired LDTM) ----------------
#define TSM_AH 1024
#define TSM_AL (1024 + 16384)
#define TSM_BH (1024 + 2 * 16384)
#define TSM_BL (1024 + 3 * 16384)
#define TC_SMEM (1024 + 4 * 16384)

__global__ __launch_bounds__(128)
void k_adj_tc(float* __restrict__ adj) {
#if HAS_TCGEN05
    extern __shared__ char smem[];
    uint32_t sb = smem_u32(smem);
    int tid = threadIdx.x, wid = tid >> 5, lid = tid & 31;
    int row0 = blockIdx.y * 128, col0 = blockIdx.x * 128;

    if (wid == 0) {
        TC_ALLOC(sb + 0, 128);
        TC_RELINQ();
    }
    if (tid == 0) MBAR_INIT(sb + 8, 1);

#pragma unroll
    for (int it = 0; it < 8; it++) {
        int idx = it * 128 + tid;
        int r = idx >> 3;
        int c = idx & 7;
        uint32_t sw = swz128((uint32_t)(r * 128 + c * 16));
        const uint4* pAh = (const uint4*)(g_zhi + (size_t)(row0 + r) * ZC) + c;
        const uint4* pAl = (const uint4*)(g_zlo + (size_t)(row0 + r) * ZC) + c;
        const uint4* pBh = (const uint4*)(g_zhi + (size_t)(col0 + r) * ZC) + c;
        const uint4* pBl = (const uint4*)(g_zlo + (size_t)(col0 + r) * ZC) + c;
        *(uint4*)(smem + TSM_AH + sw) = *pAh;
        *(uint4*)(smem + TSM_AL + sw) = *pAl;
        *(uint4*)(smem + TSM_BH + sw) = *pBh;
        *(uint4*)(smem + TSM_BL + sw) = *pBl;
    }
    FENCE_PROXY_ASYNC();
    __syncthreads();

    uint32_t tmem;
    asm volatile("ld.shared.b32 %0, [%1];" : "=r"(tmem) : "r"(sb + 0));

    if (wid == 0 && elect1()) {
        uint64_t dAh = mk_desc(sb + TSM_AH);
        uint64_t dAl = mk_desc(sb + TSM_AL);
        uint64_t dBh = mk_desc(sb + TSM_BH);
        uint64_t dBl = mk_desc(sb + TSM_BL);
        bool first = true;
#pragma unroll
        for (int p = 0; p < 3; p++) {
            uint64_t da = (p == 2) ? dAl : dAh;
            uint64_t db = (p == 1) ? dBl : dBh;
#pragma unroll
            for (int k = 0; k < 4; k++) {
                mma_f16_ss(tmem, da + k * 2, db + k * 2, TC_IDESC, !first);
                first = false;
            }
        }
        TC_COMMIT(sb + 8);
    }

    MBAR_WAIT(sb + 8, 0);
    TC_FENCE_AFTER();

    int r = row0 + wid * 32 + lid;
#pragma unroll
    for (int hp = 0; hp < 2; hp++) {
        // paired LDTM: 2 loads, one wait (dr[64] keeps regs modest)
        uint32_t dr[64];
        TC_LD_X32(dr, tmem + hp * 64);
        TC_LD_X32(dr + 32, tmem + hp * 64 + 32);
        TC_WAIT_LD();
        if (r < NN) {
            int cbase = col0 + hp * 64;
            float v[64];
#pragma unroll
            for (int j = 0; j < 64; j++)
                v[j] = 1.f / (1.f + __expf(-__uint_as_float(dr[j])));
            float* orow = adj + (size_t)r * NN + cbase;
            if (cbase + 63 < NN) {
#pragma unroll
                for (int q = 0; q < 16; q++)
                    *(float4*)(orow + q * 4) =
                        make_float4(v[q * 4], v[q * 4 + 1], v[q * 4 + 2], v[q * 4 + 3]);
            } else {
#pragma unroll
                for (int j = 0; j < 64; j++)
                    if (cbase + j < NN) orow[j] = v[j];
            }
        }
    }
    TC_FENCE_BEFORE();
    __syncthreads();
    if (tid == 0) MBAR_INVAL(sb + 8);
    __syncthreads();
    if (wid == 0) TC_DEALLOC(tmem, 128);
#endif  // HAS_TCGEN05
}

// ---------------- launcher ----------------
extern "C" void kernel_launch(void* const* d_in, const int* in_sizes, int n_in,
                              void* d_out, int out_size) {
    const float* features = (const float*)d_in[0];
    const int*   src      = (const int*)d_in[1];
    const int*   dst      = (const int*)d_in[2];
    const float* noise    = (const float*)d_in[3];
    const float* W0  = (const float*)d_in[4];
    const float* al0 = (const float*)d_in[5];
    const float* ar0 = (const float*)d_in[6];
    const float* b0  = (const float*)d_in[7];
    const float* W1  = (const float*)d_in[8];
    const float* al1 = (const float*)d_in[9];
    const float* ar1 = (const float*)d_in[10];
    const float* b1  = (const float*)d_in[11];
    const float* W2  = (const float*)d_in[12];
    const float* al2 = (const float*)d_in[13];
    const float* ar2 = (const float*)d_in[14];
    const float* b2  = (const float*)d_in[15];

    float* out = (float*)d_out;
    float* z_out = out;
    float* adj_out = out + (size_t)NN * ZC;

    void* p;
    cudaGetSymbolAddress(&p, g_lin0); float* lin0 = (float*)p;
    cudaGetSymbolAddress(&p, g_gat0); float* gat0 = (float*)p;
    cudaGetSymbolAddress(&p, g_lin1); float* lin1 = (float*)p;
    cudaGetSymbolAddress(&p, g_lin2); float* lin2 = (float*)p;
    cudaGetSymbolAddress(&p, g_mean); float* meanp = (float*)p;
    cudaGetSymbolAddress(&p, g_lstd); float* lstdp = (float*)p;
    cudaGetSymbolAddress(&p, g_el);  float* el = (float*)p;
    cudaGetSymbolAddress(&p, g_er);  float* er = (float*)p;
    cudaGetSymbolAddress(&p, g_el2); float* el2 = (float*)p;
    cudaGetSymbolAddress(&p, g_er2); float* er2 = (float*)p;

    // edge sort by dst (shared by all 3 GAT layers)
    k_zero_deg<<<(NN + 255) / 256, 256>>>();
    k_hist<<<(NE + 255) / 256, 256>>>(dst);
    k_scan<<<1, 1024>>>();
    k_scatter<<<(NE + 255) / 256, 256>>>(src, dst);

    const int ngrid = (NN * NH + 255) / 256;

    // ---- layer 0: 512 -> 256, relu (tcgen05 GEMM) ----
    k_splitx<<<(NPAD * FIN + 255) / 256, 256>>>(features);
    k_w0t<<<(HIDC * FIN + 255) / 256, 256>>>(W0);
    cudaFuncSetAttribute(k_lin0_tc, cudaFuncAttributeMaxDynamicSharedMemorySize, L_SMEM);
    k_lin0_tc<<<NPAD / 128, 128, L_SMEM>>>(lin0);
    k_elr<ND0><<<ngrid, 256>>>(lin0, al0, ar0, el, er);
    k_gat_fused<ND0, true><<<NN, HIDC>>>(lin0, el, er, b0, gat0);

    // ---- layers 1 & 2: 256 -> 64 (one dual-output launch) ----
    k_sgemm2<<<dim3(ZC / 64, (NN + 63) / 64, 2), 256>>>(gat0, W1, W2, lin1, lin2, NN, HIDC, ZC);
    k_elr<ND1><<<ngrid, 256>>>(lin1, al1, ar1, el, er);
    k_elr<ND1><<<ngrid, 256>>>(lin2, al2, ar2, el2, er2);
    k_gat_fused<ND1, false><<<NN, ZC>>>(lin1, el, er, b1, meanp);
    k_gat_fused<ND1, false><<<NN, ZC>>>(lin2, el2, er2, b2, lstdp);

    // ---- z + bf16 hi/lo split (fused, padded) ----
    k_z_split<<<(NPAD * ZC + 255) / 256, 256>>>(noise, z_out);

    // ---- adj = sigmoid(z @ z^T) via tcgen05 (round-10 config, paired LDTM) ----
    cudaFuncSetAttribute(k_adj_tc, cudaFuncAttributeMaxDynamicSharedMemorySize, TC_SMEM);
    k_adj_tc<<<dim3(NPAD / 128, NPAD / 128), 128, TC_SMEM>>>(adj_out);
}

// round 13
// speedup vs baseline: 1.1305x; 1.0531x over previous
#include <cuda_runtime.h>
#include <cuda_bf16.h>
#include <cstdint>
#include <math.h>

#define NN 10000
#define NPAD 10112           // 79 * 128
#define NE 320000
#define FIN 512
#define HIDC 256
#define ZC 64
#define NH 8
#define ND0 32
#define ND1 8
#define NEG_SLOPE 0.2f

// ---------------- scratch (static device memory; no allocations) ----------------
__device__ float g_lin0[NN * HIDC];
__device__ float g_gat0[NN * HIDC];
__device__ float g_lin1[NN * ZC];
__device__ float g_lin2[NN * ZC];
__device__ float g_mean[NN * ZC];
__device__ float g_lstd[NN * ZC];
__device__ float g_el[NN * NH];
__device__ float g_er[NN * NH];
__device__ float g_el2[NN * NH];
__device__ float g_er2[NN * NH];
__device__ float g_e[NE * NH];
__device__ int   g_deg[NN];
__device__ int   g_off[NN + 1];
__device__ int   g_cur[NN];
__device__ int   g_ssrc[NE];
__device__ __nv_bfloat16 g_zhi[NPAD * ZC];
__device__ __nv_bfloat16 g_zlo[NPAD * ZC];
__device__ __nv_bfloat16 g_xhi[NPAD * FIN];
__device__ __nv_bfloat16 g_xlo[NPAD * FIN];
__device__ __nv_bfloat16 g_w0thi[HIDC * FIN];
__device__ __nv_bfloat16 g_w0tlo[HIDC * FIN];

// Feature gate: tcgen05 only exists on the 'a' targets.
#if defined(__CUDA_ARCH_FEAT_SM103_ALL) || defined(__CUDA_ARCH_FEAT_SM100_ALL) || defined(__CUDA_ARCH_FEAT_SM101_ALL)
#define HAS_TCGEN05 1
#else
#define HAS_TCGEN05 0
#endif

// ---------------- PTX helpers ----------------
__device__ __forceinline__ uint32_t smem_u32(const void* p) {
    uint32_t a;
    asm("{ .reg .u64 t; cvta.to.shared.u64 t, %1; cvt.u32.u64 %0, t; }" : "=r"(a) : "l"(p));
    return a;
}
__device__ __forceinline__ uint32_t elect1() {
    uint32_t r;
    asm volatile("{ .reg .pred p; elect.sync _|p, 0xFFFFFFFF; selp.b32 %0,1,0,p; }" : "=r"(r));
    return r;
}
#define MBAR_INIT(mbar, cnt) \
    asm volatile("mbarrier.init.shared.b64 [%0], %1;" :: "r"((uint32_t)(mbar)), "r"((uint32_t)(cnt)) : "memory")
#define MBAR_INVAL(mbar) \
    asm volatile("mbarrier.inval.shared.b64 [%0];" :: "r"((uint32_t)(mbar)) : "memory")
#define MBAR_WAIT(mbar, parity) do {                                           \
    uint32_t _m = (uint32_t)(mbar), _p = (uint32_t)(parity), _d;               \
    asm volatile("{ .reg .pred p; mbarrier.try_wait.parity.acquire.cta.shared::cta.b64 p, [%1], %2; selp.b32 %0,1,0,p; }" \
                 : "=r"(_d) : "r"(_m), "r"(_p) : "memory");                    \
    if (!_d) {                                                                 \
        asm volatile("{ .reg .pred P1; WL%=: mbarrier.try_wait.parity.acquire.cta.shared::cta.b64 P1, [%0], %1, 0x989680; @P1 bra.uni WD%=; bra.uni WL%=; WD%=: }" \
                     :: "r"(_m), "r"(_p) : "memory");                          \
    }                                                                          \
} while (0)
#define FENCE_PROXY_ASYNC() asm volatile("fence.proxy.async.shared::cta;" ::: "memory")

#if HAS_TCGEN05
#define TC_ALLOC(saddr, n) \
    asm volatile("tcgen05.alloc.cta_group::1.sync.aligned.shared::cta.b32 [%0], %1;" \
                 :: "r"((uint32_t)(saddr)), "r"((uint32_t)(n)) : "memory")
#define TC_RELINQ() \
    asm volatile("tcgen05.relinquish_alloc_permit.cta_group::1.sync.aligned;")
#define TC_DEALLOC(tmem, n) \
    asm volatile("tcgen05.dealloc.cta_group::1.sync.aligned.b32 %0, %1;" :: "r"(tmem), "r"((uint32_t)(n)))
#define TC_COMMIT(mbar) \
    asm volatile("tcgen05.commit.cta_group::1.mbarrier::arrive::one.shared::cluster.b64 [%0];" \
                 :: "r"((uint32_t)(mbar)) : "memory")
#define TC_FENCE_AFTER() asm volatile("tcgen05.fence::after_thread_sync;" ::: "memory")
#define TC_FENCE_BEFORE() asm volatile("tcgen05.fence::before_thread_sync;" ::: "memory")
#define TC_WAIT_LD() asm volatile("tcgen05.wait::ld.sync.aligned;" ::: "memory")
#define TC_LD_X32(r, tmem_addr) \
    asm volatile( \
        "tcgen05.ld.sync.aligned.32x32b.x32.b32 " \
        "{%0, %1, %2, %3, %4, %5, %6, %7, " \
        " %8, %9, %10, %11, %12, %13, %14, %15, " \
        " %16, %17, %18, %19, %20, %21, %22, %23, " \
        " %24, %25, %26, %27, %28, %29, %30, %31}, [%32];" \
        : "=r"((r)[0]),  "=r"((r)[1]),  "=r"((r)[2]),  "=r"((r)[3]), \
          "=r"((r)[4]),  "=r"((r)[5]),  "=r"((r)[6]),  "=r"((r)[7]), \
          "=r"((r)[8]),  "=r"((r)[9]),  "=r"((r)[10]), "=r"((r)[11]), \
          "=r"((r)[12]), "=r"((r)[13]), "=r"((r)[14]), "=r"((r)[15]), \
          "=r"((r)[16]), "=r"((r)[17]), "=r"((r)[18]), "=r"((r)[19]), \
          "=r"((r)[20]), "=r"((r)[21]), "=r"((r)[22]), "=r"((r)[23]), \
          "=r"((r)[24]), "=r"((r)[25]), "=r"((r)[26]), "=r"((r)[27]), \
          "=r"((r)[28]), "=r"((r)[29]), "=r"((r)[30]), "=r"((r)[31]) \
        : "r"(tmem_addr))

__device__ __forceinline__ void mma_f16_ss(uint32_t d, uint64_t a, uint64_t b,
                                           uint32_t idesc, bool accum) {
    uint32_t en = accum ? 1u : 0u;
    asm volatile(
        "{\n\t"
        ".reg .pred p;\n\t"
        "setp.ne.u32 p, %5, 0;\n\t"
        "tcgen05.mma.cta_group::1.kind::f16 [%0], %1, %2, %3, {%4, %4, %4, %4}, p;\n\t"
        "}"
        :: "r"(d), "l"(a), "l"(b), "r"(idesc), "r"(0u), "r"(en)
        : "memory");
}
#endif  // HAS_TCGEN05

// SW128 SMEM descriptor (version=1, SBO=64, LBO=1)
__device__ __forceinline__ uint64_t mk_desc(uint32_t saddr) {
    const uint64_t BASE =
        (uint64_t(2) << 61) | (uint64_t(1) << 46) | (uint64_t(64) << 32) | (uint64_t(1) << 16);
    return BASE | ((uint64_t)(saddr >> 4) & 0x3FFF);
}
__device__ __forceinline__ uint32_t swz128(uint32_t off) {
    return off ^ ((off >> 3) & 0x70);
}

// ---------------- counting sort of edges by dst ----------------
__global__ void k_zero_deg() {
    int i = blockIdx.x * blockDim.x + threadIdx.x;
    if (i < NN) g_deg[i] = 0;
}

__global__ void k_hist(const int* __restrict__ dst) {
    int i = blockIdx.x * blockDim.x + threadIdx.x;
    if (i < NE) atomicAdd(&g_deg[dst[i]], 1);
}

__global__ void k_scan() {
    const int CH = 10;
    __shared__ int sh[1024];
    int t = threadIdx.x;
    int base = t * CH;
    int vals[CH];
    int loc = 0;
#pragma unroll
    for (int i = 0; i < CH; i++) {
        int idx = base + i;
        vals[i] = (idx < NN) ? g_deg[idx] : 0;
        loc += vals[i];
    }
    sh[t] = loc;
    __syncthreads();
    for (int off = 1; off < 1024; off <<= 1) {
        int v = (t >= off) ? sh[t - off] : 0;
        __syncthreads();
        sh[t] += v;
        __syncthreads();
    }
    int run = sh[t] - loc;
#pragma unroll
    for (int i = 0; i < CH; i++) {
        int idx = base + i;
        if (idx < NN) {
            g_off[idx] = run;
            g_cur[idx] = run;
            run += vals[i];
        }
    }
    if (t == 0) g_off[NN] = NE;
}

__global__ void k_scatter(const int* __restrict__ src, const int* __restrict__ dst) {
    int e = blockIdx.x * blockDim.x + threadIdx.x;
    if (e < NE) {
        int d = dst[e];
        int pos = atomicAdd(&g_cur[d], 1);
        g_ssrc[pos] = src[e];
    }
}

// ---------------- fp32 tiled GEMM, dual-output (layers 1/2 in one launch) ----------------
__global__ __launch_bounds__(256) void k_sgemm2(const float* __restrict__ A,
                                                const float* __restrict__ B1,
                                                const float* __restrict__ B2,
                                                float* __restrict__ C1,
                                                float* __restrict__ C2,
                                                int M, int K, int Nn) {
    const float* B = (blockIdx.z == 0) ? B1 : B2;
    float* C = (blockIdx.z == 0) ? C1 : C2;
    __shared__ float As[64 * 32];
    __shared__ float Bs[32 * 64];
    int tid = threadIdx.x;
    int tx = tid & 15, ty = tid >> 4;
    int rowBase = blockIdx.y * 64;
    int colBase = blockIdx.x * 64;
    float acc[4][4] = {};

    for (int kb = 0; kb < K; kb += 32) {
        {
            int r = tid >> 3;
            int c = (tid & 7) << 2;
#pragma unroll
            for (int p = 0; p < 2; p++) {
                int rr = r + p * 32;
                int grow = rowBase + rr;
                float4 v = make_float4(0.f, 0.f, 0.f, 0.f);
                if (grow < M) v = *(const float4*)(A + (size_t)grow * K + kb + c);
                *(float4*)(As + rr * 32 + c) = v;
            }
            int r2 = tid >> 4;
            int c2 = (tid & 15) << 2;
#pragma unroll
            for (int p = 0; p < 2; p++) {
                int rr = r2 + p * 16;
                float4 v = *(const float4*)(B + (size_t)(kb + rr) * Nn + colBase + c2);
                *(float4*)(Bs + rr * 64 + c2) = v;
            }
        }
        __syncthreads();
#pragma unroll
        for (int kk = 0; kk < 32; kk++) {
            float4 b0 = *(const float4*)(Bs + kk * 64 + tx * 4);
            float a0 = As[(ty * 4 + 0) * 32 + kk];
            float a1 = As[(ty * 4 + 1) * 32 + kk];
            float a2 = As[(ty * 4 + 2) * 32 + kk];
            float a3 = As[(ty * 4 + 3) * 32 + kk];
            acc[0][0] += a0 * b0.x; acc[0][1] += a0 * b0.y; acc[0][2] += a0 * b0.z; acc[0][3] += a0 * b0.w;
            acc[1][0] += a1 * b0.x; acc[1][1] += a1 * b0.y; acc[1][2] += a1 * b0.z; acc[1][3] += a1 * b0.w;
            acc[2][0] += a2 * b0.x; acc[2][1] += a2 * b0.y; acc[2][2] += a2 * b0.z; acc[2][3] += a2 * b0.w;
            acc[3][0] += a3 * b0.x; acc[3][1] += a3 * b0.y; acc[3][2] += a3 * b0.z; acc[3][3] += a3 * b0.w;
        }
        __syncthreads();
    }
#pragma unroll
    for (int i = 0; i < 4; i++) {
        int grow = rowBase + ty * 4 + i;
        if (grow < M) {
            *(float4*)(C + (size_t)grow * Nn + colBase + tx * 4) =
                make_float4(acc[i][0], acc[i][1], acc[i][2], acc[i][3]);
        }
    }
}

// ---------------- feature / W0^T bf16 hi-lo splits ----------------
__global__ void k_splitx(const float* __restrict__ x) {
    int i = blockIdx.x * blockDim.x + threadIdx.x;
    if (i >= NPAD * FIN) return;
    int row = i / FIN;
    float v = (row < NN) ? x[(size_t)row * FIN + (i % FIN)] : 0.f;
    __nv_bfloat16 h = __float2bfloat16(v);
    g_xhi[i] = h;
    g_xlo[i] = __float2bfloat16(v - __bfloat162float(h));
}

__global__ void k_w0t(const float* __restrict__ W0) {
    int i = blockIdx.x * blockDim.x + threadIdx.x;
    if (i >= HIDC * FIN) return;
    int n = i / FIN, k = i % FIN;
    float v = W0[(size_t)k * HIDC + n];
    __nv_bfloat16 h = __float2bfloat16(v);
    g_w0thi[i] = h;
    g_w0tlo[i] = __float2bfloat16(v - __bfloat162float(h));
}

// ---------------- lin0 = X @ W0 via tcgen05 (bf16 hi/lo, 3 passes) ----------------
#define TC_IDESC 0x8200490u
#define L_AH 1024
#define L_AL (1024 + 16384)
#define L_BH (1024 + 2 * 16384)
#define L_BL (1024 + 4 * 16384)
#define L_SMEM (1024 + 6 * 16384)

__global__ __launch_bounds__(128)
void k_lin0_tc(float* __restrict__ out) {
#if HAS_TCGEN05
    extern __shared__ char smem[];
    uint32_t sb = smem_u32(smem);
    int tid = threadIdx.x, wid = tid >> 5, lid = tid & 31;
    int row0 = blockIdx.x * 128;

    if (wid == 0) {
        TC_ALLOC(sb + 0, 256);
        TC_RELINQ();
    }
    if (tid == 0) MBAR_INIT(sb + 8, 1);
    __syncthreads();

    uint32_t tmem;
    asm volatile("ld.shared.b32 %0, [%1];" : "=r"(tmem) : "r"(sb + 0));
    uint64_t dAh = mk_desc(sb + L_AH);
    uint64_t dAl = mk_desc(sb + L_AL);
    int ph = 0;

    for (int kb = 0; kb < 8; kb++) {
        int k0 = kb * 64;
#pragma unroll
        for (int it = 0; it < 8; it++) {
            int idx = it * 128 + tid;
            int r = idx >> 3;
            int c = idx & 7;
            uint32_t sw = swz128((uint32_t)(r * 128 + c * 16));
            *(uint4*)(smem + L_AH + sw) =
                *((const uint4*)(g_xhi + (size_t)(row0 + r) * FIN + k0) + c);
            *(uint4*)(smem + L_AL + sw) =
                *((const uint4*)(g_xlo + (size_t)(row0 + r) * FIN + k0) + c);
        }
#pragma unroll
        for (int it = 0; it < 16; it++) {
            int idx = it * 128 + tid;
            int j = idx >> 10;
            int rem = idx & 1023;
            int rr = rem >> 3;
            int c = rem & 7;
            uint32_t sw = swz128((uint32_t)(rr * 128 + c * 16)) + j * 16384;
            *(uint4*)(smem + L_BH + sw) =
                *((const uint4*)(g_w0thi + (size_t)(j * 128 + rr) * FIN + k0) + c);
            *(uint4*)(smem + L_BL + sw) =
                *((const uint4*)(g_w0tlo + (size_t)(j * 128 + rr) * FIN + k0) + c);
        }
        FENCE_PROXY_ASYNC();
        __syncthreads();

        if (wid == 0 && elect1()) {
#pragma unroll
            for (int j = 0; j < 2; j++) {
                uint64_t dBh = mk_desc(sb + L_BH + j * 16384);
                uint64_t dBl = mk_desc(sb + L_BL + j * 16384);
                uint32_t dacc = tmem + j * 128;
#pragma unroll
                for (int p = 0; p < 3; p++) {
                    uint64_t da = (p == 2) ? dAl : dAh;
                    uint64_t db = (p == 1) ? dBl : dBh;
#pragma unroll
                    for (int k = 0; k < 4; k++) {
                        bool first = (kb == 0) && (p == 0) && (k == 0);
                        mma_f16_ss(dacc, da + k * 2, db + k * 2, TC_IDESC, !first);
                    }
                }
            }
            TC_COMMIT(sb + 8);
        }
        MBAR_WAIT(sb + 8, ph & 1);
        ph++;
        __syncthreads();
    }

    TC_FENCE_AFTER();
    int r = row0 + wid * 32 + lid;
#pragma unroll
    for (int j = 0; j < 2; j++) {
#pragma unroll
        for (int ch = 0; ch < 4; ch++) {
            uint32_t dr[32];
            TC_LD_X32(dr, tmem + j * 128 + ch * 32);
            TC_WAIT_LD();
            if (r < NN) {
                float* orow = out + (size_t)r * HIDC + j * 128 + ch * 32;
#pragma unroll
                for (int q = 0; q < 8; q++)
                    *(float4*)(orow + q * 4) = make_float4(
                        __uint_as_float(dr[q * 4]), __uint_as_float(dr[q * 4 + 1]),
                        __uint_as_float(dr[q * 4 + 2]), __uint_as_float(dr[q * 4 + 3]));
            }
        }
    }
    TC_FENCE_BEFORE();
    __syncthreads();
    if (tid == 0) MBAR_INVAL(sb + 8);
    __syncthreads();
    if (wid == 0) TC_DEALLOC(tmem, 256);
#endif  // HAS_TCGEN05
}

// ---------------- el/er ----------------
template <int D>
__global__ void k_elr(const float* __restrict__ lin,
                      const float* __restrict__ al,
                      const float* __restrict__ ar,
                      float* __restrict__ elo, float* __restrict__ ero) {
    int i = blockIdx.x * blockDim.x + threadIdx.x;
    if (i >= NN * NH) return;
    int n = i / NH, h = i % NH;
    float el = 0.f, er = 0.f;
#pragma unroll
    for (int d = 0; d < D; d++) {
        float v = lin[n * (NH * D) + h * D + d];
        el += v * al[h * D + d];
        er += v * ar[h * D + d];
    }
    elo[i] = el;
    ero[i] = er;
}

// ---------------- fused per-node GAT ----------------
template <int D, bool RELU>
__global__ void k_gat_fused(const float* __restrict__ lin,
                            const float* __restrict__ elp,
                            const float* __restrict__ erp,
                            const float* __restrict__ bias,
                            float* __restrict__ out) {
    const int C = NH * D;
    int n = blockIdx.x;
    int tid = threadIdx.x;
    int beg = g_off[n], end = g_off[n + 1];
    __shared__ int   s_m[NH];
    __shared__ float s_sum[NH];
    __shared__ int   s_src[32];
    __shared__ float s_ex[32 * NH];
    if (tid < NH) { s_m[tid] = __float_as_int(-INFINITY); s_sum[tid] = 0.f; }
    __syncthreads();

    {
        int h = tid & 7;
        float ern = erp[n * NH + h];
        for (int j0 = beg + (tid >> 3); j0 < end; j0 += C / NH) {
            int s = g_ssrc[j0];
            float v = elp[s * NH + h] + ern;
            v = (v > 0.f) ? v : NEG_SLOPE * v;
            g_e[(size_t)j0 * NH + h] = v;
            if (v >= 0.f)
                atomicMax(&s_m[h], __float_as_int(v));
            else
                atomicMin((unsigned int*)&s_m[h], (unsigned int)__float_as_int(v));
        }
    }
    __syncthreads();

    float acc = 0.f;
    int hA = tid / D;
    for (int base = beg; base < end; base += 32) {
        int cnt = min(32, end - base);
        __syncthreads();
        if (tid < cnt) s_src[tid] = g_ssrc[base + tid];
        for (int i = tid; i < cnt * NH; i += C) {
            float ex = __expf(g_e[(size_t)base * NH + i] - __int_as_float(s_m[i & 7]));
            s_ex[i] = ex;
            atomicAdd(&s_sum[i & 7], ex);
        }
        __syncthreads();
        for (int jj = 0; jj < cnt; jj++)
            acc += lin[(size_t)s_src[jj] * C + tid] * s_ex[jj * NH + hA];
    }
    float v = (end > beg) ? acc / s_sum[hA] : 0.f;
    v += bias[tid];
    if (RELU) v = fmaxf(v, 0.f);
    out[(size_t)n * C + tid] = v;
}

// ---------------- z = mean + noise*exp(log_std); fused bf16 hi/lo split ----------------
__global__ void k_z_split(const float* __restrict__ noise, float* __restrict__ zout) {
    int i = blockIdx.x * blockDim.x + threadIdx.x;
    if (i >= NPAD * ZC) return;
    float v = 0.f;
    if (i < NN * ZC) {
        v = g_mean[i] + noise[i] * expf(g_lstd[i]);
        zout[i] = v;
    }
    __nv_bfloat16 h = __float2bfloat16(v);
    g_zhi[i] = h;
    g_zlo[i] = __float2bfloat16(v - __bfloat162float(h));
}

// ---------------- adj = sigmoid(z @ z^T) via tcgen05 (round-10 proven config) ----------------
#define TSM_AH 1024
#define TSM_AL (1024 + 16384)
#define TSM_BH (1024 + 2 * 16384)
#define TSM_BL (1024 + 3 * 16384)
#define TC_SMEM (1024 + 4 * 16384)

__global__ __launch_bounds__(128)
void k_adj_tc(float* __restrict__ adj) {
#if HAS_TCGEN05
    extern __shared__ char smem[];
    uint32_t sb = smem_u32(smem);
    int tid = threadIdx.x, wid = tid >> 5, lid = tid & 31;
    int row0 = blockIdx.y * 128, col0 = blockIdx.x * 128;

    if (wid == 0) {
        TC_ALLOC(sb + 0, 128);
        TC_RELINQ();
    }
    if (tid == 0) MBAR_INIT(sb + 8, 1);

#pragma unroll
    for (int it = 0; it < 8; it++) {
        int idx = it * 128 + tid;
        int r = idx >> 3;
        int c = idx & 7;
        uint32_t sw = swz128((uint32_t)(r * 128 + c * 16));
        const uint4* pAh = (const uint4*)(g_zhi + (size_t)(row0 + r) * ZC) + c;
        const uint4* pAl = (const uint4*)(g_zlo + (size_t)(row0 + r) * ZC) + c;
        const uint4* pBh = (const uint4*)(g_zhi + (size_t)(col0 + r) * ZC) + c;
        const uint4* pBl = (const uint4*)(g_zlo + (size_t)(col0 + r) * ZC) + c;
        *(uint4*)(smem + TSM_AH + sw) = *pAh;
        *(uint4*)(smem + TSM_AL + sw) = *pAl;
        *(uint4*)(smem + TSM_BH + sw) = *pBh;
        *(uint4*)(smem + TSM_BL + sw) = *pBl;
    }
    __syncthreads();

    uint32_t tmem;
    asm volatile("ld.shared.b32 %0, [%1];" : "=r"(tmem) : "r"(sb + 0));

    if (wid == 0 && elect1()) {
        uint64_t dAh = mk_desc(sb + TSM_AH);
        uint64_t dAl = mk_desc(sb + TSM_AL);
        uint64_t dBh = mk_desc(sb + TSM_BH);
        uint64_t dBl = mk_desc(sb + TSM_BL);
        bool first = true;
#pragma unroll
        for (int p = 0; p < 3; p++) {
            uint64_t da = (p == 2) ? dAl : dAh;
            uint64_t db = (p == 1) ? dBl : dBh;
#pragma unroll
            for (int k = 0; k < 4; k++) {
                mma_f16_ss(tmem, da + k * 2, db + k * 2, TC_IDESC, !first);
                first = false;
            }
        }
        TC_COMMIT(sb + 8);
    }

    MBAR_WAIT(sb + 8, 0);
    TC_FENCE_AFTER();

    int r = row0 + wid * 32 + lid;
#pragma unroll
    for (int ch = 0; ch < 4; ch++) {
        uint32_t dr[32];
        TC_LD_X32(dr, tmem + ch * 32);
        TC_WAIT_LD();
        if (r < NN) {
            int cbase = col0 + ch * 32;
            float v[32];
#pragma unroll
            for (int j = 0; j < 32; j++)
                v[j] = 1.f / (1.f + __expf(-__uint_as_float(dr[j])));
            float* orow = adj + (size_t)r * NN + cbase;
            if (cbase + 31 < NN) {
#pragma unroll
                for (int q = 0; q < 8; q++)
                    *(float4*)(orow + q * 4) =
                        make_float4(v[q * 4], v[q * 4 + 1], v[q * 4 + 2], v[q * 4 + 3]);
            } else {
#pragma unroll
                for (int j = 0; j < 32; j++)
                    if (cbase + j < NN) orow[j] = v[j];
            }
        }
    }
    TC_FENCE_BEFORE();
    __syncthreads();
    if (tid == 0) MBAR_INVAL(sb + 8);
    __syncthreads();
    if (wid == 0) TC_DEALLOC(tmem, 128);
#endif  // HAS_TCGEN05
}

// ---------------- launcher ----------------
extern "C" void kernel_launch(void* const* d_in, const int* in_sizes, int n_in,
                              void* d_out, int out_size) {
    const float* features = (const float*)d_in[0];
    const int*   src      = (const int*)d_in[1];
    const int*   dst      = (const int*)d_in[2];
    const float* noise    = (const float*)d_in[3];
    const float* W0  = (const float*)d_in[4];
    const float* al0 = (const float*)d_in[5];
    const float* ar0 = (const float*)d_in[6];
    const float* b0  = (const float*)d_in[7];
    const float* W1  = (const float*)d_in[8];
    const float* al1 = (const float*)d_in[9];
    const float* ar1 = (const float*)d_in[10];
    const float* b1  = (const float*)d_in[11];
    const float* W2  = (const float*)d_in[12];
    const float* al2 = (const float*)d_in[13];
    const float* ar2 = (const float*)d_in[14];
    const float* b2  = (const float*)d_in[15];

    float* out = (float*)d_out;
    float* z_out = out;
    float* adj_out = out + (size_t)NN * ZC;

    void* p;
    cudaGetSymbolAddress(&p, g_lin0); float* lin0 = (float*)p;
    cudaGetSymbolAddress(&p, g_gat0); float* gat0 = (float*)p;
    cudaGetSymbolAddress(&p, g_lin1); float* lin1 = (float*)p;
    cudaGetSymbolAddress(&p, g_lin2); float* lin2 = (float*)p;
    cudaGetSymbolAddress(&p, g_mean); float* meanp = (float*)p;
    cudaGetSymbolAddress(&p, g_lstd); float* lstdp = (float*)p;
    cudaGetSymbolAddress(&p, g_el);  float* el = (float*)p;
    cudaGetSymbolAddress(&p, g_er);  float* er = (float*)p;
    cudaGetSymbolAddress(&p, g_el2); float* el2 = (float*)p;
    cudaGetSymbolAddress(&p, g_er2); float* er2 = (float*)p;

    // edge sort by dst (shared by all 3 GAT layers)
    k_zero_deg<<<(NN + 255) / 256, 256>>>();
    k_hist<<<(NE + 255) / 256, 256>>>(dst);
    k_scan<<<1, 1024>>>();
    k_scatter<<<(NE + 255) / 256, 256>>>(src, dst);

    const int ngrid = (NN * NH + 255) / 256;

    // ---- layer 0: 512 -> 256, relu (tcgen05 GEMM) ----
    k_splitx<<<(NPAD * FIN + 255) / 256, 256>>>(features);
    k_w0t<<<(HIDC * FIN + 255) / 256, 256>>>(W0);
    cudaFuncSetAttribute(k_lin0_tc, cudaFuncAttributeMaxDynamicSharedMemorySize, L_SMEM);
    k_lin0_tc<<<NPAD / 128, 128, L_SMEM>>>(lin0);
    k_elr<ND0><<<ngrid, 256>>>(lin0, al0, ar0, el, er);
    k_gat_fused<ND0, true><<<NN, HIDC>>>(lin0, el, er, b0, gat0);

    // ---- layers 1 & 2: 256 -> 64 (one dual-output launch) ----
    k_sgemm2<<<dim3(ZC / 64, (NN + 63) / 64, 2), 256>>>(gat0, W1, W2, lin1, lin2, NN, HIDC, ZC);
    k_elr<ND1><<<ngrid, 256>>>(lin1, al1, ar1, el, er);
    k_elr<ND1><<<ngrid, 256>>>(lin2, al2, ar2, el2, er2);
    k_gat_fused<ND1, false><<<NN, ZC>>>(lin1, el, er, b1, meanp);
    k_gat_fused<ND1, false><<<NN, ZC>>>(lin2, el2, er2, b2, lstdp);

    // ---- z + bf16 hi/lo split (fused, padded) ----
    k_z_split<<<(NPAD * ZC + 255) / 256, 256>>>(noise, z_out);

    // ---- adj = sigmoid(z @ z^T) via tcgen05 (round-10 config) ----
    cudaFuncSetAttribute(k_adj_tc, cudaFuncAttributeMaxDynamicSharedMemorySize, TC_SMEM);
    k_adj_tc<<<dim3(NPAD / 128, NPAD / 128), 128, TC_SMEM>>>(adj_out);
}

// round 14
// speedup vs baseline: 1.2416x; 1.0982x over previous
#include <cuda_runtime.h>
#include <cuda_bf16.h>
#include <cstdint>
#include <math.h>

#define NN 10000
#define NPAD 10112           // 79 * 128
#define NE 320000
#define FIN 512
#define HIDC 256
#define ZC 64
#define NH 8
#define ND0 32
#define ND1 8
#define NEG_SLOPE 0.2f

// ---------------- scratch (static device memory; no allocations) ----------------
__device__ float g_lin0[NN * HIDC];
__device__ float g_gat0[NN * HIDC];
__device__ float g_lin1[NN * ZC];
__device__ float g_lin2[NN * ZC];
__device__ float g_mean[NN * ZC];
__device__ float g_lstd[NN * ZC];
__device__ float g_el[NN * NH];
__device__ float g_er[NN * NH];
__device__ float g_el2[NN * NH];
__device__ float g_er2[NN * NH];
__device__ float g_e[NE * NH];
__device__ int   g_deg[NN];
__device__ int   g_off[NN + 1];
__device__ int   g_cur[NN];
__device__ int   g_ssrc[NE];
__device__ __nv_bfloat16 g_zhi[NPAD * ZC];
__device__ __nv_bfloat16 g_zlo[NPAD * ZC];
__device__ __nv_bfloat16 g_xhi[NPAD * FIN];
__device__ __nv_bfloat16 g_xlo[NPAD * FIN];
__device__ __nv_bfloat16 g_w0thi[HIDC * FIN];
__device__ __nv_bfloat16 g_w0tlo[HIDC * FIN];

// Feature gate: tcgen05 only exists on the 'a' targets.
#if defined(__CUDA_ARCH_FEAT_SM103_ALL) || defined(__CUDA_ARCH_FEAT_SM100_ALL) || defined(__CUDA_ARCH_FEAT_SM101_ALL)
#define HAS_TCGEN05 1
#else
#define HAS_TCGEN05 0
#endif

// ---------------- PTX helpers ----------------
__device__ __forceinline__ uint32_t smem_u32(const void* p) {
    uint32_t a;
    asm("{ .reg .u64 t; cvta.to.shared.u64 t, %1; cvt.u32.u64 %0, t; }" : "=r"(a) : "l"(p));
    return a;
}
__device__ __forceinline__ uint32_t elect1() {
    uint32_t r;
    asm volatile("{ .reg .pred p; elect.sync _|p, 0xFFFFFFFF; selp.b32 %0,1,0,p; }" : "=r"(r));
    return r;
}
#define MBAR_INIT(mbar, cnt) \
    asm volatile("mbarrier.init.shared.b64 [%0], %1;" :: "r"((uint32_t)(mbar)), "r"((uint32_t)(cnt)) : "memory")
#define MBAR_INVAL(mbar) \
    asm volatile("mbarrier.inval.shared.b64 [%0];" :: "r"((uint32_t)(mbar)) : "memory")
#define MBAR_WAIT(mbar, parity) do {                                           \
    uint32_t _m = (uint32_t)(mbar), _p = (uint32_t)(parity), _d;               \
    asm volatile("{ .reg .pred p; mbarrier.try_wait.parity.acquire.cta.shared::cta.b64 p, [%1], %2; selp.b32 %0,1,0,p; }" \
                 : "=r"(_d) : "r"(_m), "r"(_p) : "memory");                    \
    if (!_d) {                                                                 \
        asm volatile("{ .reg .pred P1; WL%=: mbarrier.try_wait.parity.acquire.cta.shared::cta.b64 P1, [%0], %1, 0x989680; @P1 bra.uni WD%=; bra.uni WL%=; WD%=: }" \
                     :: "r"(_m), "r"(_p) : "memory");                          \
    }                                                                          \
} while (0)
#define FENCE_PROXY_ASYNC() asm volatile("fence.proxy.async.shared::cta;" ::: "memory")

#if HAS_TCGEN05
#define TC_ALLOC(saddr, n) \
    asm volatile("tcgen05.alloc.cta_group::1.sync.aligned.shared::cta.b32 [%0], %1;" \
                 :: "r"((uint32_t)(saddr)), "r"((uint32_t)(n)) : "memory")
#define TC_RELINQ() \
    asm volatile("tcgen05.relinquish_alloc_permit.cta_group::1.sync.aligned;")
#define TC_DEALLOC(tmem, n) \
    asm volatile("tcgen05.dealloc.cta_group::1.sync.aligned.b32 %0, %1;" :: "r"(tmem), "r"((uint32_t)(n)))
#define TC_COMMIT(mbar) \
    asm volatile("tcgen05.commit.cta_group::1.mbarrier::arrive::one.shared::cluster.b64 [%0];" \
                 :: "r"((uint32_t)(mbar)) : "memory")
#define TC_FENCE_AFTER() asm volatile("tcgen05.fence::after_thread_sync;" ::: "memory")
#define TC_FENCE_BEFORE() asm volatile("tcgen05.fence::before_thread_sync;" ::: "memory")
#define TC_WAIT_LD() asm volatile("tcgen05.wait::ld.sync.aligned;" ::: "memory")
#define TC_LD_X32(r, tmem_addr) \
    asm volatile( \
        "tcgen05.ld.sync.aligned.32x32b.x32.b32 " \
        "{%0, %1, %2, %3, %4, %5, %6, %7, " \
        " %8, %9, %10, %11, %12, %13, %14, %15, " \
        " %16, %17, %18, %19, %20, %21, %22, %23, " \
        " %24, %25, %26, %27, %28, %29, %30, %31}, [%32];" \
        : "=r"((r)[0]),  "=r"((r)[1]),  "=r"((r)[2]),  "=r"((r)[3]), \
          "=r"((r)[4]),  "=r"((r)[5]),  "=r"((r)[6]),  "=r"((r)[7]), \
          "=r"((r)[8]),  "=r"((r)[9]),  "=r"((r)[10]), "=r"((r)[11]), \
          "=r"((r)[12]), "=r"((r)[13]), "=r"((r)[14]), "=r"((r)[15]), \
          "=r"((r)[16]), "=r"((r)[17]), "=r"((r)[18]), "=r"((r)[19]), \
          "=r"((r)[20]), "=r"((r)[21]), "=r"((r)[22]), "=r"((r)[23]), \
          "=r"((r)[24]), "=r"((r)[25]), "=r"((r)[26]), "=r"((r)[27]), \
          "=r"((r)[28]), "=r"((r)[29]), "=r"((r)[30]), "=r"((r)[31]) \
        : "r"(tmem_addr))

__device__ __forceinline__ void mma_f16_ss(uint32_t d, uint64_t a, uint64_t b,
                                           uint32_t idesc, bool accum) {
    uint32_t en = accum ? 1u : 0u;
    asm volatile(
        "{\n\t"
        ".reg .pred p;\n\t"
        "setp.ne.u32 p, %5, 0;\n\t"
        "tcgen05.mma.cta_group::1.kind::f16 [%0], %1, %2, %3, {%4, %4, %4, %4}, p;\n\t"
        "}"
        :: "r"(d), "l"(a), "l"(b), "r"(idesc), "r"(0u), "r"(en)
        : "memory");
}
#endif  // HAS_TCGEN05

// SW128 SMEM descriptor (version=1, SBO=64, LBO=1)
__device__ __forceinline__ uint64_t mk_desc(uint32_t saddr) {
    const uint64_t BASE =
        (uint64_t(2) << 61) | (uint64_t(1) << 46) | (uint64_t(64) << 32) | (uint64_t(1) << 16);
    return BASE | ((uint64_t)(saddr >> 4) & 0x3FFF);
}
__device__ __forceinline__ uint32_t swz128(uint32_t off) {
    return off ^ ((off >> 3) & 0x70);
}

// ---------------- counting sort of edges by dst ----------------
__global__ void k_zero_deg() {
    int i = blockIdx.x * blockDim.x + threadIdx.x;
    if (i < NN) g_deg[i] = 0;
}

__global__ void k_hist(const int* __restrict__ dst) {
    int i = blockIdx.x * blockDim.x + threadIdx.x;
    if (i < NE) atomicAdd(&g_deg[dst[i]], 1);
}

__global__ void k_scan() {
    const int CH = 10;
    __shared__ int sh[1024];
    int t = threadIdx.x;
    int base = t * CH;
    int vals[CH];
    int loc = 0;
#pragma unroll
    for (int i = 0; i < CH; i++) {
        int idx = base + i;
        vals[i] = (idx < NN) ? g_deg[idx] : 0;
        loc += vals[i];
    }
    sh[t] = loc;
    __syncthreads();
    for (int off = 1; off < 1024; off <<= 1) {
        int v = (t >= off) ? sh[t - off] : 0;
        __syncthreads();
        sh[t] += v;
        __syncthreads();
    }
    int run = sh[t] - loc;
#pragma unroll
    for (int i = 0; i < CH; i++) {
        int idx = base + i;
        if (idx < NN) {
            g_off[idx] = run;
            g_cur[idx] = run;
            run += vals[i];
        }
    }
    if (t == 0) g_off[NN] = NE;
}

__global__ void k_scatter(const int* __restrict__ src, const int* __restrict__ dst) {
    int e = blockIdx.x * blockDim.x + threadIdx.x;
    if (e < NE) {
        int d = dst[e];
        int pos = atomicAdd(&g_cur[d], 1);
        g_ssrc[pos] = src[e];
    }
}

// ---------------- fp32 tiled GEMM, dual-output (layers 1/2 in one launch) ----------------
__global__ __launch_bounds__(256) void k_sgemm2(const float* __restrict__ A,
                                                const float* __restrict__ B1,
                                                const float* __restrict__ B2,
                                                float* __restrict__ C1,
                                                float* __restrict__ C2,
                                                int M, int K, int Nn) {
    const float* B = (blockIdx.z == 0) ? B1 : B2;
    float* C = (blockIdx.z == 0) ? C1 : C2;
    __shared__ float As[64 * 32];
    __shared__ float Bs[32 * 64];
    int tid = threadIdx.x;
    int tx = tid & 15, ty = tid >> 4;
    int rowBase = blockIdx.y * 64;
    int colBase = blockIdx.x * 64;
    float acc[4][4] = {};

    for (int kb = 0; kb < K; kb += 32) {
        {
            int r = tid >> 3;
            int c = (tid & 7) << 2;
#pragma unroll
            for (int p = 0; p < 2; p++) {
                int rr = r + p * 32;
                int grow = rowBase + rr;
                float4 v = make_float4(0.f, 0.f, 0.f, 0.f);
                if (grow < M) v = *(const float4*)(A + (size_t)grow * K + kb + c);
                *(float4*)(As + rr * 32 + c) = v;
            }
            int r2 = tid >> 4;
            int c2 = (tid & 15) << 2;
#pragma unroll
            for (int p = 0; p < 2; p++) {
                int rr = r2 + p * 16;
                float4 v = *(const float4*)(B + (size_t)(kb + rr) * Nn + colBase + c2);
                *(float4*)(Bs + rr * 64 + c2) = v;
            }
        }
        __syncthreads();
#pragma unroll
        for (int kk = 0; kk < 32; kk++) {
            float4 b0 = *(const float4*)(Bs + kk * 64 + tx * 4);
            float a0 = As[(ty * 4 + 0) * 32 + kk];
            float a1 = As[(ty * 4 + 1) * 32 + kk];
            float a2 = As[(ty * 4 + 2) * 32 + kk];
            float a3 = As[(ty * 4 + 3) * 32 + kk];
            acc[0][0] += a0 * b0.x; acc[0][1] += a0 * b0.y; acc[0][2] += a0 * b0.z; acc[0][3] += a0 * b0.w;
            acc[1][0] += a1 * b0.x; acc[1][1] += a1 * b0.y; acc[1][2] += a1 * b0.z; acc[1][3] += a1 * b0.w;
            acc[2][0] += a2 * b0.x; acc[2][1] += a2 * b0.y; acc[2][2] += a2 * b0.z; acc[2][3] += a2 * b0.w;
            acc[3][0] += a3 * b0.x; acc[3][1] += a3 * b0.y; acc[3][2] += a3 * b0.z; acc[3][3] += a3 * b0.w;
        }
        __syncthreads();
    }
#pragma unroll
    for (int i = 0; i < 4; i++) {
        int grow = rowBase + ty * 4 + i;
        if (grow < M) {
            *(float4*)(C + (size_t)grow * Nn + colBase + tx * 4) =
                make_float4(acc[i][0], acc[i][1], acc[i][2], acc[i][3]);
        }
    }
}

// ---------------- feature / W0^T bf16 hi-lo splits ----------------
__global__ void k_splitx(const float* __restrict__ x) {
    int i = blockIdx.x * blockDim.x + threadIdx.x;
    if (i >= NPAD * FIN) return;
    int row = i / FIN;
    float v = (row < NN) ? x[(size_t)row * FIN + (i % FIN)] : 0.f;
    __nv_bfloat16 h = __float2bfloat16(v);
    g_xhi[i] = h;
    g_xlo[i] = __float2bfloat16(v - __bfloat162float(h));
}

__global__ void k_w0t(const float* __restrict__ W0) {
    int i = blockIdx.x * blockDim.x + threadIdx.x;
    if (i >= HIDC * FIN) return;
    int n = i / FIN, k = i % FIN;
    float v = W0[(size_t)k * HIDC + n];
    __nv_bfloat16 h = __float2bfloat16(v);
    g_w0thi[i] = h;
    g_w0tlo[i] = __float2bfloat16(v - __bfloat162float(h));
}

// ---------------- lin0 = X @ W0 via tcgen05; fused layer-0 el/er epilogue ----------------
#define TC_IDESC 0x8200490u
#define L_AH 1024
#define L_AL (1024 + 16384)
#define L_BH (1024 + 2 * 16384)
#define L_BL (1024 + 4 * 16384)
#define L_SMEM (1024 + 6 * 16384)

__global__ __launch_bounds__(128)
void k_lin0_tc(float* __restrict__ out,
               const float* __restrict__ al0,
               const float* __restrict__ ar0) {
#if HAS_TCGEN05
    extern __shared__ char smem[];
    uint32_t sb = smem_u32(smem);
    int tid = threadIdx.x, wid = tid >> 5, lid = tid & 31;
    int row0 = blockIdx.x * 128;

    if (wid == 0) {
        TC_ALLOC(sb + 0, 256);
        TC_RELINQ();
    }
    if (tid == 0) MBAR_INIT(sb + 8, 1);
    __syncthreads();

    uint32_t tmem;
    asm volatile("ld.shared.b32 %0, [%1];" : "=r"(tmem) : "r"(sb + 0));
    uint64_t dAh = mk_desc(sb + L_AH);
    uint64_t dAl = mk_desc(sb + L_AL);
    int ph = 0;

    for (int kb = 0; kb < 8; kb++) {
        int k0 = kb * 64;
#pragma unroll
        for (int it = 0; it < 8; it++) {
            int idx = it * 128 + tid;
            int r = idx >> 3;
            int c = idx & 7;
            uint32_t sw = swz128((uint32_t)(r * 128 + c * 16));
            *(uint4*)(smem + L_AH + sw) =
                *((const uint4*)(g_xhi + (size_t)(row0 + r) * FIN + k0) + c);
            *(uint4*)(smem + L_AL + sw) =
                *((const uint4*)(g_xlo + (size_t)(row0 + r) * FIN + k0) + c);
        }
#pragma unroll
        for (int it = 0; it < 16; it++) {
            int idx = it * 128 + tid;
            int j = idx >> 10;
            int rem = idx & 1023;
            int rr = rem >> 3;
            int c = rem & 7;
            uint32_t sw = swz128((uint32_t)(rr * 128 + c * 16)) + j * 16384;
            *(uint4*)(smem + L_BH + sw) =
                *((const uint4*)(g_w0thi + (size_t)(j * 128 + rr) * FIN + k0) + c);
            *(uint4*)(smem + L_BL + sw) =
                *((const uint4*)(g_w0tlo + (size_t)(j * 128 + rr) * FIN + k0) + c);
        }
        FENCE_PROXY_ASYNC();
        __syncthreads();

        if (wid == 0 && elect1()) {
#pragma unroll
            for (int j = 0; j < 2; j++) {
                uint64_t dBh = mk_desc(sb + L_BH + j * 16384);
                uint64_t dBl = mk_desc(sb + L_BL + j * 16384);
                uint32_t dacc = tmem + j * 128;
#pragma unroll
                for (int p = 0; p < 3; p++) {
                    uint64_t da = (p == 2) ? dAl : dAh;
                    uint64_t db = (p == 1) ? dBl : dBh;
#pragma unroll
                    for (int k = 0; k < 4; k++) {
                        bool first = (kb == 0) && (p == 0) && (k == 0);
                        mma_f16_ss(dacc, da + k * 2, db + k * 2, TC_IDESC, !first);
                    }
                }
            }
            TC_COMMIT(sb + 8);
        }
        MBAR_WAIT(sb + 8, ph & 1);
        ph++;
        __syncthreads();
    }

    TC_FENCE_AFTER();
    int r = row0 + wid * 32 + lid;
#pragma unroll
    for (int j = 0; j < 2; j++) {
#pragma unroll
        for (int ch = 0; ch < 4; ch++) {
            uint32_t dr[32];
            TC_LD_X32(dr, tmem + j * 128 + ch * 32);
            TC_WAIT_LD();
            if (r < NN) {
                int hd = j * 4 + ch;     // chunk == one head (D0=32)
                float el = 0.f, er = 0.f;
                float* orow = out + (size_t)r * HIDC + hd * 32;
#pragma unroll
                for (int q = 0; q < 8; q++) {
                    float4 v = make_float4(
                        __uint_as_float(dr[q * 4]), __uint_as_float(dr[q * 4 + 1]),
                        __uint_as_float(dr[q * 4 + 2]), __uint_as_float(dr[q * 4 + 3]));
                    *(float4*)(orow + q * 4) = v;
                    const float4 a4 = *(const float4*)(al0 + hd * 32 + q * 4);
                    const float4 r4 = *(const float4*)(ar0 + hd * 32 + q * 4);
                    el += v.x * a4.x + v.y * a4.y + v.z * a4.z + v.w * a4.w;
                    er += v.x * r4.x + v.y * r4.y + v.z * r4.z + v.w * r4.w;
                }
                g_el[r * NH + hd] = el;
                g_er[r * NH + hd] = er;
            }
        }
    }
    TC_FENCE_BEFORE();
    __syncthreads();
    if (tid == 0) MBAR_INVAL(sb + 8);
    __syncthreads();
    if (wid == 0) TC_DEALLOC(tmem, 256);
#endif  // HAS_TCGEN05
}

// ---------------- el/er (layers 1/2) ----------------
template <int D>
__global__ void k_elr(const float* __restrict__ lin,
                      const float* __restrict__ al,
                      const float* __restrict__ ar,
                      float* __restrict__ elo, float* __restrict__ ero) {
    int i = blockIdx.x * blockDim.x + threadIdx.x;
    if (i >= NN * NH) return;
    int n = i / NH, h = i % NH;
    float el = 0.f, er = 0.f;
#pragma unroll
    for (int d = 0; d < D; d++) {
        float v = lin[n * (NH * D) + h * D + d];
        el += v * al[h * D + d];
        er += v * ar[h * D + d];
    }
    elo[i] = el;
    ero[i] = er;
}

// ---------------- fused per-node GAT, float4 aggregation (layer 0) ----------------
// 64 threads per node; thread owns 4 channels (one head = threads 8t..8t+7).
__global__ void k_gat_fused4(const float* __restrict__ lin,
                             const float* __restrict__ elp,
                             const float* __restrict__ erp,
                             const float* __restrict__ bias,
                             float* __restrict__ out) {
    int n = blockIdx.x;
    int tid = threadIdx.x;   // 0..63
    int beg = g_off[n], end = g_off[n + 1];
    int hA = tid >> 3;       // head of this thread's 4 channels
    __shared__ int   s_m[NH];
    __shared__ float s_sum[NH];
    __shared__ int   s_src[32];
    __shared__ float s_ex[32 * NH];
    if (tid < NH) { s_m[tid] = __float_as_int(-INFINITY); s_sum[tid] = 0.f; }
    __syncthreads();

    // pass 1: e = leaky_relu(el[src]+er[n]); block max per head
    {
        int h = tid & 7;
        float ern = erp[n * NH + h];
        for (int j0 = beg + (tid >> 3); j0 < end; j0 += 8) {
            int s = g_ssrc[j0];
            float v = elp[s * NH + h] + ern;
            v = (v > 0.f) ? v : NEG_SLOPE * v;
            g_e[(size_t)j0 * NH + h] = v;
            if (v >= 0.f)
                atomicMax(&s_m[h], __float_as_int(v));
            else
                atomicMin((unsigned int*)&s_m[h], (unsigned int)__float_as_int(v));
        }
    }
    __syncthreads();

    // pass 2: exp + sum + aggregate (float4)
    float4 acc = make_float4(0.f, 0.f, 0.f, 0.f);
    for (int base = beg; base < end; base += 32) {
        int cnt = min(32, end - base);
        __syncthreads();
        if (tid < cnt) s_src[tid] = g_ssrc[base + tid];
        for (int i = tid; i < cnt * NH; i += 64) {
            float ex = __expf(g_e[(size_t)base * NH + i] - __int_as_float(s_m[i & 7]));
            s_ex[i] = ex;
            atomicAdd(&s_sum[i & 7], ex);
        }
        __syncthreads();
        for (int jj = 0; jj < cnt; jj++) {
            float w = s_ex[jj * NH + hA];
            float4 l = *(const float4*)(lin + (size_t)s_src[jj] * HIDC + tid * 4);
            acc.x += l.x * w; acc.y += l.y * w; acc.z += l.z * w; acc.w += l.w * w;
        }
    }
    float inv = (end > beg) ? 1.f / s_sum[hA] : 0.f;
    float4 b4 = *(const float4*)(bias + tid * 4);
    float4 v;
    v.x = fmaxf(acc.x * inv + b4.x, 0.f);
    v.y = fmaxf(acc.y * inv + b4.y, 0.f);
    v.z = fmaxf(acc.z * inv + b4.z, 0.f);
    v.w = fmaxf(acc.w * inv + b4.w, 0.f);
    *(float4*)(out + (size_t)n * HIDC + tid * 4) = v;
}

// ---------------- fused per-node GAT (layers 1/2, scalar, C=64) ----------------
template <int D, bool RELU>
__global__ void k_gat_fused(const float* __restrict__ lin,
                            const float* __restrict__ elp,
                            const float* __restrict__ erp,
                            const float* __restrict__ bias,
                            float* __restrict__ out) {
    const int C = NH * D;
    int n = blockIdx.x;
    int tid = threadIdx.x;
    int beg = g_off[n], end = g_off[n + 1];
    __shared__ int   s_m[NH];
    __shared__ float s_sum[NH];
    __shared__ int   s_src[32];
    __shared__ float s_ex[32 * NH];
    if (tid < NH) { s_m[tid] = __float_as_int(-INFINITY); s_sum[tid] = 0.f; }
    __syncthreads();

    {
        int h = tid & 7;
        float ern = erp[n * NH + h];
        for (int j0 = beg + (tid >> 3); j0 < end; j0 += C / NH) {
            int s = g_ssrc[j0];
            float v = elp[s * NH + h] + ern;
            v = (v > 0.f) ? v : NEG_SLOPE * v;
            g_e[(size_t)j0 * NH + h] = v;
            if (v >= 0.f)
                atomicMax(&s_m[h], __float_as_int(v));
            else
                atomicMin((unsigned int*)&s_m[h], (unsigned int)__float_as_int(v));
        }
    }
    __syncthreads();

    float acc = 0.f;
    int hA = tid / D;
    for (int base = beg; base < end; base += 32) {
        int cnt = min(32, end - base);
        __syncthreads();
        if (tid < cnt) s_src[tid] = g_ssrc[base + tid];
        for (int i = tid; i < cnt * NH; i += C) {
            float ex = __expf(g_e[(size_t)base * NH + i] - __int_as_float(s_m[i & 7]));
            s_ex[i] = ex;
            atomicAdd(&s_sum[i & 7], ex);
        }
        __syncthreads();
        for (int jj = 0; jj < cnt; jj++)
            acc += lin[(size_t)s_src[jj] * C + tid] * s_ex[jj * NH + hA];
    }
    float v = (end > beg) ? acc / s_sum[hA] : 0.f;
    v += bias[tid];
    if (RELU) v = fmaxf(v, 0.f);
    out[(size_t)n * C + tid] = v;
}

// ---------------- z = mean + noise*exp(log_std); fused bf16 hi/lo split ----------------
__global__ void k_z_split(const float* __restrict__ noise, float* __restrict__ zout) {
    int i = blockIdx.x * blockDim.x + threadIdx.x;
    if (i >= NPAD * ZC) return;
    float v = 0.f;
    if (i < NN * ZC) {
        v = g_mean[i] + noise[i] * expf(g_lstd[i]);
        zout[i] = v;
    }
    __nv_bfloat16 h = __float2bfloat16(v);
    g_zhi[i] = h;
    g_zlo[i] = __float2bfloat16(v - __bfloat162float(h));
}

// ---------------- adj = sigmoid(z @ z^T) via tcgen05 (round-10 proven config) ----------------
#define TSM_AH 1024
#define TSM_AL (1024 + 16384)
#define TSM_BH (1024 + 2 * 16384)
#define TSM_BL (1024 + 3 * 16384)
#define TC_SMEM (1024 + 4 * 16384)

__global__ __launch_bounds__(128)
void k_adj_tc(float* __restrict__ adj) {
#if HAS_TCGEN05
    extern __shared__ char smem[];
    uint32_t sb = smem_u32(smem);
    int tid = threadIdx.x, wid = tid >> 5, lid = tid & 31;
    int row0 = blockIdx.y * 128, col0 = blockIdx.x * 128;

    if (wid == 0) {
        TC_ALLOC(sb + 0, 128);
        TC_RELINQ();
    }
    if (tid == 0) MBAR_INIT(sb + 8, 1);

#pragma unroll
    for (int it = 0; it < 8; it++) {
        int idx = it * 128 + tid;
        int r = idx >> 3;
        int c = idx & 7;
        uint32_t sw = swz128((uint32_t)(r * 128 + c * 16));
        const uint4* pAh = (const uint4*)(g_zhi + (size_t)(row0 + r) * ZC) + c;
        const uint4* pAl = (const uint4*)(g_zlo + (size_t)(row0 + r) * ZC) + c;
        const uint4* pBh = (const uint4*)(g_zhi + (size_t)(col0 + r) * ZC) + c;
        const uint4* pBl = (const uint4*)(g_zlo + (size_t)(col0 + r) * ZC) + c;
        *(uint4*)(smem + TSM_AH + sw) = *pAh;
        *(uint4*)(smem + TSM_AL + sw) = *pAl;
        *(uint4*)(smem + TSM_BH + sw) = *pBh;
        *(uint4*)(smem + TSM_BL + sw) = *pBl;
    }
    __syncthreads();

    uint32_t tmem;
    asm volatile("ld.shared.b32 %0, [%1];" : "=r"(tmem) : "r"(sb + 0));

    if (wid == 0 && elect1()) {
        uint64_t dAh = mk_desc(sb + TSM_AH);
        uint64_t dAl = mk_desc(sb + TSM_AL);
        uint64_t dBh = mk_desc(sb + TSM_BH);
        uint64_t dBl = mk_desc(sb + TSM_BL);
        bool first = true;
#pragma unroll
        for (int p = 0; p < 3; p++) {
            uint64_t da = (p == 2) ? dAl : dAh;
            uint64_t db = (p == 1) ? dBl : dBh;
#pragma unroll
            for (int k = 0; k < 4; k++) {
                mma_f16_ss(tmem, da + k * 2, db + k * 2, TC_IDESC, !first);
                first = false;
            }
        }
        TC_COMMIT(sb + 8);
    }

    MBAR_WAIT(sb + 8, 0);
    TC_FENCE_AFTER();

    int r = row0 + wid * 32 + lid;
#pragma unroll
    for (int ch = 0; ch < 4; ch++) {
        uint32_t dr[32];
        TC_LD_X32(dr, tmem + ch * 32);
        TC_WAIT_LD();
        if (r < NN) {
            int cbase = col0 + ch * 32;
            float v[32];
#pragma unroll
            for (int j = 0; j < 32; j++)
                v[j] = 1.f / (1.f + __expf(-__uint_as_float(dr[j])));
            float* orow = adj + (size_t)r * NN + cbase;
            if (cbase + 31 < NN) {
#pragma unroll
                for (int q = 0; q < 8; q++)
                    *(float4*)(orow + q * 4) =
                        make_float4(v[q * 4], v[q * 4 + 1], v[q * 4 + 2], v[q * 4 + 3]);
            } else {
#pragma unroll
                for (int j = 0; j < 32; j++)
                    if (cbase + j < NN) orow[j] = v[j];
            }
        }
    }
    TC_FENCE_BEFORE();
    __syncthreads();
    if (tid == 0) MBAR_INVAL(sb + 8);
    __syncthreads();
    if (wid == 0) TC_DEALLOC(tmem, 128);
#endif  // HAS_TCGEN05
}

// ---------------- launcher ----------------
extern "C" void kernel_launch(void* const* d_in, const int* in_sizes, int n_in,
                              void* d_out, int out_size) {
    const float* features = (const float*)d_in[0];
    const int*   src      = (const int*)d_in[1];
    const int*   dst      = (const int*)d_in[2];
    const float* noise    = (const float*)d_in[3];
    const float* W0  = (const float*)d_in[4];
    const float* al0 = (const float*)d_in[5];
    const float* ar0 = (const float*)d_in[6];
    const float* b0  = (const float*)d_in[7];
    const float* W1  = (const float*)d_in[8];
    const float* al1 = (const float*)d_in[9];
    const float* ar1 = (const float*)d_in[10];
    const float* b1  = (const float*)d_in[11];
    const float* W2  = (const float*)d_in[12];
    const float* al2 = (const float*)d_in[13];
    const float* ar2 = (const float*)d_in[14];
    const float* b2  = (const float*)d_in[15];

    float* out = (float*)d_out;
    float* z_out = out;
    float* adj_out = out + (size_t)NN * ZC;

    void* p;
    cudaGetSymbolAddress(&p, g_lin0); float* lin0 = (float*)p;
    cudaGetSymbolAddress(&p, g_gat0); float* gat0 = (float*)p;
    cudaGetSymbolAddress(&p, g_lin1); float* lin1 = (float*)p;
    cudaGetSymbolAddress(&p, g_lin2); float* lin2 = (float*)p;
    cudaGetSymbolAddress(&p, g_mean); float* meanp = (float*)p;
    cudaGetSymbolAddress(&p, g_lstd); float* lstdp = (float*)p;
    cudaGetSymbolAddress(&p, g_el);  float* el = (float*)p;
    cudaGetSymbolAddress(&p, g_er);  float* er = (float*)p;
    cudaGetSymbolAddress(&p, g_el2); float* el2 = (float*)p;
    cudaGetSymbolAddress(&p, g_er2); float* er2 = (float*)p;

    // edge sort by dst (shared by all 3 GAT layers)
    k_zero_deg<<<(NN + 255) / 256, 256>>>();
    k_hist<<<(NE + 255) / 256, 256>>>(dst);
    k_scan<<<1, 1024>>>();
    k_scatter<<<(NE + 255) / 256, 256>>>(src, dst);

    const int ngrid = (NN * NH + 255) / 256;

    // ---- layer 0: 512 -> 256, relu (tcgen05 GEMM + fused el/er epilogue) ----
    k_splitx<<<(NPAD * FIN + 255) / 256, 256>>>(features);
    k_w0t<<<(HIDC * FIN + 255) / 256, 256>>>(W0);
    cudaFuncSetAttribute(k_lin0_tc, cudaFuncAttributeMaxDynamicSharedMemorySize, L_SMEM);
    k_lin0_tc<<<NPAD / 128, 128, L_SMEM>>>(lin0, al0, ar0);
    k_gat_fused4<<<NN, 64>>>(lin0, el, er, b0, gat0);

    // ---- layers 1 & 2: 256 -> 64 (one dual-output launch) ----
    k_sgemm2<<<dim3(ZC / 64, (NN + 63) / 64, 2), 256>>>(gat0, W1, W2, lin1, lin2, NN, HIDC, ZC);
    k_elr<ND1><<<ngrid, 256>>>(lin1, al1, ar1, el, er);
    k_elr<ND1><<<ngrid, 256>>>(lin2, al2, ar2, el2, er2);
    k_gat_fused<ND1, false><<<NN, ZC>>>(lin1, el, er, b1, meanp);
    k_gat_fused<ND1, false><<<NN, ZC>>>(lin2, el2, er2, b2, lstdp);

    // ---- z + bf16 hi/lo split (fused, padded) ----
    k_z_split<<<(NPAD * ZC + 255) / 256, 256>>>(noise, z_out);

    // ---- adj = sigmoid(z @ z^T) via tcgen05 (round-10 config) ----
    cudaFuncSetAttribute(k_adj_tc, cudaFuncAttributeMaxDynamicSharedMemorySize, TC_SMEM);
    k_adj_tc<<<dim3(NPAD / 128, NPAD / 128), 128, TC_SMEM>>>(adj_out);
}

// round 16
// speedup vs baseline: 1.2673x; 1.0207x over previous
#include <cuda_runtime.h>
#include <cuda_bf16.h>
#include <cstdint>
#include <math.h>

#define NN 10000
#define NPAD 10112           // 79 * 128
#define NE 320000
#define FIN 512
#define HIDC 256
#define ZC 64
#define NH 8
#define ND0 32
#define ND1 8
#define NEG_SLOPE 0.2f

// ---------------- scratch (static device memory; no allocations) ----------------
__device__ float g_lin0[NN * HIDC];
__device__ float g_gat0[NN * HIDC];
__device__ float g_lin1[NN * ZC];
__device__ float g_lin2[NN * ZC];
__device__ float g_mean[NN * ZC];
__device__ float g_lstd[NN * ZC];
__device__ float g_el[NN * NH];
__device__ float g_er[NN * NH];
__device__ float g_el2[NN * NH];
__device__ float g_er2[NN * NH];
__device__ float g_e[NE * NH];
__device__ int   g_deg[NN];
__device__ int   g_off[NN + 1];
__device__ int   g_cur[NN];
__device__ int   g_ssrc[NE];
__device__ __nv_bfloat16 g_zhi[NPAD * ZC];
__device__ __nv_bfloat16 g_zlo[NPAD * ZC];
__device__ __nv_bfloat16 g_xhi[NPAD * FIN];
__device__ __nv_bfloat16 g_xlo[NPAD * FIN];
__device__ __nv_bfloat16 g_w0thi[HIDC * FIN];
__device__ __nv_bfloat16 g_w0tlo[HIDC * FIN];

// Feature gate: tcgen05 only exists on the 'a' targets.
#if defined(__CUDA_ARCH_FEAT_SM103_ALL) || defined(__CUDA_ARCH_FEAT_SM100_ALL) || defined(__CUDA_ARCH_FEAT_SM101_ALL)
#define HAS_TCGEN05 1
#else
#define HAS_TCGEN05 0
#endif

// ---------------- PTX helpers ----------------
__device__ __forceinline__ uint32_t smem_u32(const void* p) {
    uint32_t a;
    asm("{ .reg .u64 t; cvta.to.shared.u64 t, %1; cvt.u32.u64 %0, t; }" : "=r"(a) : "l"(p));
    return a;
}
__device__ __forceinline__ uint32_t elect1() {
    uint32_t r;
    asm volatile("{ .reg .pred p; elect.sync _|p, 0xFFFFFFFF; selp.b32 %0,1,0,p; }" : "=r"(r));
    return r;
}
#define MBAR_INIT(mbar, cnt) \
    asm volatile("mbarrier.init.shared.b64 [%0], %1;" :: "r"((uint32_t)(mbar)), "r"((uint32_t)(cnt)) : "memory")
#define MBAR_INVAL(mbar) \
    asm volatile("mbarrier.inval.shared.b64 [%0];" :: "r"((uint32_t)(mbar)) : "memory")
#define MBAR_WAIT(mbar, parity) do {                                           \
    uint32_t _m = (uint32_t)(mbar), _p = (uint32_t)(parity), _d;               \
    asm volatile("{ .reg .pred p; mbarrier.try_wait.parity.acquire.cta.shared::cta.b64 p, [%1], %2; selp.b32 %0,1,0,p; }" \
                 : "=r"(_d) : "r"(_m), "r"(_p) : "memory");                    \
    if (!_d) {                                                                 \
        asm volatile("{ .reg .pred P1; WL%=: mbarrier.try_wait.parity.acquire.cta.shared::cta.b64 P1, [%0], %1, 0x989680; @P1 bra.uni WD%=; bra.uni WL%=; WD%=: }" \
                     :: "r"(_m), "r"(_p) : "memory");                          \
    }                                                                          \
} while (0)
#define FENCE_PROXY_ASYNC() asm volatile("fence.proxy.async.shared::cta;" ::: "memory")

#if HAS_TCGEN05
#define TC_ALLOC(saddr, n) \
    asm volatile("tcgen05.alloc.cta_group::1.sync.aligned.shared::cta.b32 [%0], %1;" \
                 :: "r"((uint32_t)(saddr)), "r"((uint32_t)(n)) : "memory")
#define TC_RELINQ() \
    asm volatile("tcgen05.relinquish_alloc_permit.cta_group::1.sync.aligned;")
#define TC_DEALLOC(tmem, n) \
    asm volatile("tcgen05.dealloc.cta_group::1.sync.aligned.b32 %0, %1;" :: "r"(tmem), "r"((uint32_t)(n)))
#define TC_COMMIT(mbar) \
    asm volatile("tcgen05.commit.cta_group::1.mbarrier::arrive::one.shared::cluster.b64 [%0];" \
                 :: "r"((uint32_t)(mbar)) : "memory")
#define TC_FENCE_AFTER() asm volatile("tcgen05.fence::after_thread_sync;" ::: "memory")
#define TC_FENCE_BEFORE() asm volatile("tcgen05.fence::before_thread_sync;" ::: "memory")
#define TC_WAIT_LD() asm volatile("tcgen05.wait::ld.sync.aligned;" ::: "memory")
#define TC_LD_X32(r, tmem_addr) \
    asm volatile( \
        "tcgen05.ld.sync.aligned.32x32b.x32.b32 " \
        "{%0, %1, %2, %3, %4, %5, %6, %7, " \
        " %8, %9, %10, %11, %12, %13, %14, %15, " \
        " %16, %17, %18, %19, %20, %21, %22, %23, " \
        " %24, %25, %26, %27, %28, %29, %30, %31}, [%32];" \
        : "=r"((r)[0]),  "=r"((r)[1]),  "=r"((r)[2]),  "=r"((r)[3]), \
          "=r"((r)[4]),  "=r"((r)[5]),  "=r"((r)[6]),  "=r"((r)[7]), \
          "=r"((r)[8]),  "=r"((r)[9]),  "=r"((r)[10]), "=r"((r)[11]), \
          "=r"((r)[12]), "=r"((r)[13]), "=r"((r)[14]), "=r"((r)[15]), \
          "=r"((r)[16]), "=r"((r)[17]), "=r"((r)[18]), "=r"((r)[19]), \
          "=r"((r)[20]), "=r"((r)[21]), "=r"((r)[22]), "=r"((r)[23]), \
          "=r"((r)[24]), "=r"((r)[25]), "=r"((r)[26]), "=r"((r)[27]), \
          "=r"((r)[28]), "=r"((r)[29]), "=r"((r)[30]), "=r"((r)[31]) \
        : "r"(tmem_addr))

__device__ __forceinline__ void mma_f16_ss(uint32_t d, uint64_t a, uint64_t b,
                                           uint32_t idesc, bool accum) {
    uint32_t en = accum ? 1u : 0u;
    asm volatile(
        "{\n\t"
        ".reg .pred p;\n\t"
        "setp.ne.u32 p, %5, 0;\n\t"
        "tcgen05.mma.cta_group::1.kind::f16 [%0], %1, %2, %3, {%4, %4, %4, %4}, p;\n\t"
        "}"
        :: "r"(d), "l"(a), "l"(b), "r"(idesc), "r"(0u), "r"(en)
        : "memory");
}
#endif  // HAS_TCGEN05

// SW128 SMEM descriptor (version=1, SBO=64, LBO=1)
__device__ __forceinline__ uint64_t mk_desc(uint32_t saddr) {
    const uint64_t BASE =
        (uint64_t(2) << 61) | (uint64_t(1) << 46) | (uint64_t(64) << 32) | (uint64_t(1) << 16);
    return BASE | ((uint64_t)(saddr >> 4) & 0x3FFF);
}
__device__ __forceinline__ uint32_t swz128(uint32_t off) {
    return off ^ ((off >> 3) & 0x70);
}

// ---------------- counting sort of edges by dst ----------------
__global__ void k_zero_deg() {
    int i = blockIdx.x * blockDim.x + threadIdx.x;
    if (i < NN) g_deg[i] = 0;
}

__global__ void k_hist(const int* __restrict__ dst) {
    int i = blockIdx.x * blockDim.x + threadIdx.x;
    if (i < NE) atomicAdd(&g_deg[dst[i]], 1);
}

__global__ void k_scan() {
    const int CH = 10;
    __shared__ int sh[1024];
    int t = threadIdx.x;
    int base = t * CH;
    int vals[CH];
    int loc = 0;
#pragma unroll
    for (int i = 0; i < CH; i++) {
        int idx = base + i;
        vals[i] = (idx < NN) ? g_deg[idx] : 0;
        loc += vals[i];
    }
    sh[t] = loc;
    __syncthreads();
    for (int off = 1; off < 1024; off <<= 1) {
        int v = (t >= off) ? sh[t - off] : 0;
        __syncthreads();
        sh[t] += v;
        __syncthreads();
    }
    int run = sh[t] - loc;
#pragma unroll
    for (int i = 0; i < CH; i++) {
        int idx = base + i;
        if (idx < NN) {
            g_off[idx] = run;
            g_cur[idx] = run;
            run += vals[i];
        }
    }
    if (t == 0) g_off[NN] = NE;
}

__global__ void k_scatter(const int* __restrict__ src, const int* __restrict__ dst) {
    int e = blockIdx.x * blockDim.x + threadIdx.x;
    if (e < NE) {
        int d = dst[e];
        int pos = atomicAdd(&g_cur[d], 1);
        g_ssrc[pos] = src[e];
    }
}

// ---------------- fp32 tiled GEMM, dual-output + fused el/er (layers 1/2) ----------------
// Nn == 64: one block spans the full row width, so el/er reduce locally.
__global__ __launch_bounds__(256) void k_sgemm2(const float* __restrict__ A,
                                                const float* __restrict__ B1,
                                                const float* __restrict__ B2,
                                                float* __restrict__ C1,
                                                float* __restrict__ C2,
                                                const float* __restrict__ al1,
                                                const float* __restrict__ ar1,
                                                const float* __restrict__ al2,
                                                const float* __restrict__ ar2,
                                                float* __restrict__ el1o,
                                                float* __restrict__ er1o,
                                                float* __restrict__ el2o,
                                                float* __restrict__ er2o,
                                                int M, int K, int Nn) {
    const float* B = (blockIdx.z == 0) ? B1 : B2;
    float* C = (blockIdx.z == 0) ? C1 : C2;
    const float* al = (blockIdx.z == 0) ? al1 : al2;
    const float* ar = (blockIdx.z == 0) ? ar1 : ar2;
    float* elo = (blockIdx.z == 0) ? el1o : el2o;
    float* ero = (blockIdx.z == 0) ? er1o : er2o;
    __shared__ float As[64 * 32];
    __shared__ float Bs[32 * 64];
    __shared__ float s_el[64][NH];
    __shared__ float s_er[64][NH];
    int tid = threadIdx.x;
    int tx = tid & 15, ty = tid >> 4;
    int rowBase = blockIdx.y * 64;
    int colBase = blockIdx.x * 64;
    float acc[4][4] = {};

    for (int i = tid; i < 64 * NH; i += 256) {
        ((float*)s_el)[i] = 0.f;
        ((float*)s_er)[i] = 0.f;
    }

    for (int kb = 0; kb < K; kb += 32) {
        {
            int r = tid >> 3;
            int c = (tid & 7) << 2;
#pragma unroll
            for (int p = 0; p < 2; p++) {
                int rr = r + p * 32;
                int grow = rowBase + rr;
                float4 v = make_float4(0.f, 0.f, 0.f, 0.f);
                if (grow < M) v = *(const float4*)(A + (size_t)grow * K + kb + c);
                *(float4*)(As + rr * 32 + c) = v;
            }
            int r2 = tid >> 4;
            int c2 = (tid & 15) << 2;
#pragma unroll
            for (int p = 0; p < 2; p++) {
                int rr = r2 + p * 16;
                float4 v = *(const float4*)(B + (size_t)(kb + rr) * Nn + colBase + c2);
                *(float4*)(Bs + rr * 64 + c2) = v;
            }
        }
        __syncthreads();
#pragma unroll
        for (int kk = 0; kk < 32; kk++) {
            float4 b0 = *(const float4*)(Bs + kk * 64 + tx * 4);
            float a0 = As[(ty * 4 + 0) * 32 + kk];
            float a1 = As[(ty * 4 + 1) * 32 + kk];
            float a2 = As[(ty * 4 + 2) * 32 + kk];
            float a3 = As[(ty * 4 + 3) * 32 + kk];
            acc[0][0] += a0 * b0.x; acc[0][1] += a0 * b0.y; acc[0][2] += a0 * b0.z; acc[0][3] += a0 * b0.w;
            acc[1][0] += a1 * b0.x; acc[1][1] += a1 * b0.y; acc[1][2] += a1 * b0.z; acc[1][3] += a1 * b0.w;
            acc[2][0] += a2 * b0.x; acc[2][1] += a2 * b0.y; acc[2][2] += a2 * b0.z; acc[2][3] += a2 * b0.w;
            acc[3][0] += a3 * b0.x; acc[3][1] += a3 * b0.y; acc[3][2] += a3 * b0.z; acc[3][3] += a3 * b0.w;
        }
        __syncthreads();
    }
#pragma unroll
    for (int i = 0; i < 4; i++) {
        int grow = rowBase + ty * 4 + i;
        if (grow < M) {
            *(float4*)(C + (size_t)grow * Nn + colBase + tx * 4) =
                make_float4(acc[i][0], acc[i][1], acc[i][2], acc[i][3]);
        }
    }

    // fused el/er: this thread's 4 cols (tx*4..tx*4+3) all lie in head tx>>1
    {
        float elp[4] = {}, erp[4] = {};
#pragma unroll
        for (int j = 0; j < 4; j++) {
            float a = al[tx * 4 + j];
            float rr = ar[tx * 4 + j];
#pragma unroll
            for (int i = 0; i < 4; i++) {
                elp[i] += acc[i][j] * a;
                erp[i] += acc[i][j] * rr;
            }
        }
        int h = tx >> 1;
#pragma unroll
        for (int i = 0; i < 4; i++) {
            atomicAdd(&s_el[ty * 4 + i][h], elp[i]);
            atomicAdd(&s_er[ty * 4 + i][h], erp[i]);
        }
    }
    __syncthreads();
    // FIX (round 15 bug): strided loop, 512 entries > 256 threads
    for (int i = tid; i < 64 * NH; i += 256) {
        int rloc = i >> 3, hh = i & 7;
        int grow = rowBase + rloc;
        if (grow < M) {
            elo[grow * NH + hh] = s_el[rloc][hh];
            ero[grow * NH + hh] = s_er[rloc][hh];
        }
    }
}

// ---------------- feature / W0^T bf16 hi-lo splits ----------------
__global__ void k_splitx(const float* __restrict__ x) {
    int i = blockIdx.x * blockDim.x + threadIdx.x;
    if (i >= NPAD * FIN) return;
    int row = i / FIN;
    float v = (row < NN) ? x[(size_t)row * FIN + (i % FIN)] : 0.f;
    __nv_bfloat16 h = __float2bfloat16(v);
    g_xhi[i] = h;
    g_xlo[i] = __float2bfloat16(v - __bfloat162float(h));
}

__global__ void k_w0t(const float* __restrict__ W0) {
    int i = blockIdx.x * blockDim.x + threadIdx.x;
    if (i >= HIDC * FIN) return;
    int n = i / FIN, k = i % FIN;
    float v = W0[(size_t)k * HIDC + n];
    __nv_bfloat16 h = __float2bfloat16(v);
    g_w0thi[i] = h;
    g_w0tlo[i] = __float2bfloat16(v - __bfloat162float(h));
}

// ---------------- lin0 = X @ W0 via tcgen05; fused layer-0 el/er epilogue ----------------
#define TC_IDESC 0x8200490u
#define L_AH 1024
#define L_AL (1024 + 16384)
#define L_BH (1024 + 2 * 16384)
#define L_BL (1024 + 4 * 16384)
#define L_SMEM (1024 + 6 * 16384)

__global__ __launch_bounds__(128)
void k_lin0_tc(float* __restrict__ out,
               const float* __restrict__ al0,
               const float* __restrict__ ar0) {
#if HAS_TCGEN05
    extern __shared__ char smem[];
    uint32_t sb = smem_u32(smem);
    int tid = threadIdx.x, wid = tid >> 5, lid = tid & 31;
    int row0 = blockIdx.x * 128;

    if (wid == 0) {
        TC_ALLOC(sb + 0, 256);
        TC_RELINQ();
    }
    if (tid == 0) MBAR_INIT(sb + 8, 1);
    __syncthreads();

    uint32_t tmem;
    asm volatile("ld.shared.b32 %0, [%1];" : "=r"(tmem) : "r"(sb + 0));
    uint64_t dAh = mk_desc(sb + L_AH);
    uint64_t dAl = mk_desc(sb + L_AL);
    int ph = 0;

    for (int kb = 0; kb < 8; kb++) {
        int k0 = kb * 64;
#pragma unroll
        for (int it = 0; it < 8; it++) {
            int idx = it * 128 + tid;
            int r = idx >> 3;
            int c = idx & 7;
            uint32_t sw = swz128((uint32_t)(r * 128 + c * 16));
            *(uint4*)(smem + L_AH + sw) =
                *((const uint4*)(g_xhi + (size_t)(row0 + r) * FIN + k0) + c);
            *(uint4*)(smem + L_AL + sw) =
                *((const uint4*)(g_xlo + (size_t)(row0 + r) * FIN + k0) + c);
        }
#pragma unroll
        for (int it = 0; it < 16; it++) {
            int idx = it * 128 + tid;
            int j = idx >> 10;
            int rem = idx & 1023;
            int rr = rem >> 3;
            int c = rem & 7;
            uint32_t sw = swz128((uint32_t)(rr * 128 + c * 16)) + j * 16384;
            *(uint4*)(smem + L_BH + sw) =
                *((const uint4*)(g_w0thi + (size_t)(j * 128 + rr) * FIN + k0) + c);
            *(uint4*)(smem + L_BL + sw) =
                *((const uint4*)(g_w0tlo + (size_t)(j * 128 + rr) * FIN + k0) + c);
        }
        FENCE_PROXY_ASYNC();
        __syncthreads();

        if (wid == 0 && elect1()) {
#pragma unroll
            for (int j = 0; j < 2; j++) {
                uint64_t dBh = mk_desc(sb + L_BH + j * 16384);
                uint64_t dBl = mk_desc(sb + L_BL + j * 16384);
                uint32_t dacc = tmem + j * 128;
#pragma unroll
                for (int p = 0; p < 3; p++) {
                    uint64_t da = (p == 2) ? dAl : dAh;
                    uint64_t db = (p == 1) ? dBl : dBh;
#pragma unroll
                    for (int k = 0; k < 4; k++) {
                        bool first = (kb == 0) && (p == 0) && (k == 0);
                        mma_f16_ss(dacc, da + k * 2, db + k * 2, TC_IDESC, !first);
                    }
                }
            }
            TC_COMMIT(sb + 8);
        }
        MBAR_WAIT(sb + 8, ph & 1);
        ph++;
        __syncthreads();
    }

    TC_FENCE_AFTER();
    int r = row0 + wid * 32 + lid;
#pragma unroll
    for (int j = 0; j < 2; j++) {
#pragma unroll
        for (int ch = 0; ch < 4; ch++) {
            uint32_t dr[32];
            TC_LD_X32(dr, tmem + j * 128 + ch * 32);
            TC_WAIT_LD();
            if (r < NN) {
                int hd = j * 4 + ch;     // chunk == one head (D0=32)
                float el = 0.f, er = 0.f;
                float* orow = out + (size_t)r * HIDC + hd * 32;
#pragma unroll
                for (int q = 0; q < 8; q++) {
                    float4 v = make_float4(
                        __uint_as_float(dr[q * 4]), __uint_as_float(dr[q * 4 + 1]),
                        __uint_as_float(dr[q * 4 + 2]), __uint_as_float(dr[q * 4 + 3]));
                    *(float4*)(orow + q * 4) = v;
                    const float4 a4 = *(const float4*)(al0 + hd * 32 + q * 4);
                    const float4 r4 = *(const float4*)(ar0 + hd * 32 + q * 4);
                    el += v.x * a4.x + v.y * a4.y + v.z * a4.z + v.w * a4.w;
                    er += v.x * r4.x + v.y * r4.y + v.z * r4.z + v.w * r4.w;
                }
                g_el[r * NH + hd] = el;
                g_er[r * NH + hd] = er;
            }
        }
    }
    TC_FENCE_BEFORE();
    __syncthreads();
    if (tid == 0) MBAR_INVAL(sb + 8);
    __syncthreads();
    if (wid == 0) TC_DEALLOC(tmem, 256);
#endif  // HAS_TCGEN05
}

// ---------------- fused per-node GAT, float4 aggregation (layer 0) ----------------
__global__ void k_gat_fused4(const float* __restrict__ lin,
                             const float* __restrict__ elp,
                             const float* __restrict__ erp,
                             const float* __restrict__ bias,
                             float* __restrict__ out) {
    int n = blockIdx.x;
    int tid = threadIdx.x;   // 0..63
    int beg = g_off[n], end = g_off[n + 1];
    int hA = tid >> 3;
    __shared__ int   s_m[NH];
    __shared__ float s_sum[NH];
    __shared__ int   s_src[32];
    __shared__ float s_ex[32 * NH];
    if (tid < NH) { s_m[tid] = __float_as_int(-INFINITY); s_sum[tid] = 0.f; }
    __syncthreads();

    {
        int h = tid & 7;
        float ern = erp[n * NH + h];
        for (int j0 = beg + (tid >> 3); j0 < end; j0 += 8) {
            int s = g_ssrc[j0];
            float v = elp[s * NH + h] + ern;
            v = (v > 0.f) ? v : NEG_SLOPE * v;
            g_e[(size_t)j0 * NH + h] = v;
            if (v >= 0.f)
                atomicMax(&s_m[h], __float_as_int(v));
            else
                atomicMin((unsigned int*)&s_m[h], (unsigned int)__float_as_int(v));
        }
    }
    __syncthreads();

    float4 acc = make_float4(0.f, 0.f, 0.f, 0.f);
    for (int base = beg; base < end; base += 32) {
        int cnt = min(32, end - base);
        __syncthreads();
        if (tid < cnt) s_src[tid] = g_ssrc[base + tid];
        for (int i = tid; i < cnt * NH; i += 64) {
            float ex = __expf(g_e[(size_t)base * NH + i] - __int_as_float(s_m[i & 7]));
            s_ex[i] = ex;
            atomicAdd(&s_sum[i & 7], ex);
        }
        __syncthreads();
        for (int jj = 0; jj < cnt; jj++) {
            float w = s_ex[jj * NH + hA];
            float4 l = *(const float4*)(lin + (size_t)s_src[jj] * HIDC + tid * 4);
            acc.x += l.x * w; acc.y += l.y * w; acc.z += l.z * w; acc.w += l.w * w;
        }
    }
    float inv = (end > beg) ? 1.f / s_sum[hA] : 0.f;
    float4 b4 = *(const float4*)(bias + tid * 4);
    float4 v;
    v.x = fmaxf(acc.x * inv + b4.x, 0.f);
    v.y = fmaxf(acc.y * inv + b4.y, 0.f);
    v.z = fmaxf(acc.z * inv + b4.z, 0.f);
    v.w = fmaxf(acc.w * inv + b4.w, 0.f);
    *(float4*)(out + (size_t)n * HIDC + tid * 4) = v;
}

// ---------------- fused per-node GAT (layers 1/2, scalar, C=64) ----------------
template <int D, bool RELU>
__global__ void k_gat_fused(const float* __restrict__ lin,
                            const float* __restrict__ elp,
                            const float* __restrict__ erp,
                            const float* __restrict__ bias,
                            float* __restrict__ out) {
    const int C = NH * D;
    int n = blockIdx.x;
    int tid = threadIdx.x;
    int beg = g_off[n], end = g_off[n + 1];
    __shared__ int   s_m[NH];
    __shared__ float s_sum[NH];
    __shared__ int   s_src[32];
    __shared__ float s_ex[32 * NH];
    if (tid < NH) { s_m[tid] = __float_as_int(-INFINITY); s_sum[tid] = 0.f; }
    __syncthreads();

    {
        int h = tid & 7;
        float ern = erp[n * NH + h];
        for (int j0 = beg + (tid >> 3); j0 < end; j0 += C / NH) {
            int s = g_ssrc[j0];
            float v = elp[s * NH + h] + ern;
            v = (v > 0.f) ? v : NEG_SLOPE * v;
            g_e[(size_t)j0 * NH + h] = v;
            if (v >= 0.f)
                atomicMax(&s_m[h], __float_as_int(v));
            else
                atomicMin((unsigned int*)&s_m[h], (unsigned int)__float_as_int(v));
        }
    }
    __syncthreads();

    float acc = 0.f;
    int hA = tid / D;
    for (int base = beg; base < end; base += 32) {
        int cnt = min(32, end - base);
        __syncthreads();
        if (tid < cnt) s_src[tid] = g_ssrc[base + tid];
        for (int i = tid; i < cnt * NH; i += C) {
            float ex = __expf(g_e[(size_t)base * NH + i] - __int_as_float(s_m[i & 7]));
            s_ex[i] = ex;
            atomicAdd(&s_sum[i & 7], ex);
        }
        __syncthreads();
        for (int jj = 0; jj < cnt; jj++)
            acc += lin[(size_t)s_src[jj] * C + tid] * s_ex[jj * NH + hA];
    }
    float v = (end > beg) ? acc / s_sum[hA] : 0.f;
    v += bias[tid];
    if (RELU) v = fmaxf(v, 0.f);
    out[(size_t)n * C + tid] = v;
}

// ---------------- z = mean + noise*exp(log_std); fused bf16 hi/lo split ----------------
__global__ void k_z_split(const float* __restrict__ noise, float* __restrict__ zout) {
    int i = blockIdx.x * blockDim.x + threadIdx.x;
    if (i >= NPAD * ZC) return;
    float v = 0.f;
    if (i < NN * ZC) {
        v = g_mean[i] + noise[i] * expf(g_lstd[i]);
        zout[i] = v;
    }
    __nv_bfloat16 h = __float2bfloat16(v);
    g_zhi[i] = h;
    g_zlo[i] = __float2bfloat16(v - __bfloat162float(h));
}

// ---------------- adj = sigmoid(z @ z^T) via tcgen05, 256 threads / split epilogue ----------------
#define TSM_AH 1024
#define TSM_AL (1024 + 16384)
#define TSM_BH (1024 + 2 * 16384)
#define TSM_BL (1024 + 3 * 16384)
#define TC_SMEM (1024 + 4 * 16384)

__global__ __launch_bounds__(256)
void k_adj_tc(float* __restrict__ adj) {
#if HAS_TCGEN05
    extern __shared__ char smem[];
    uint32_t sb = smem_u32(smem);
    int tid = threadIdx.x, wid = tid >> 5, lid = tid & 31;
    int row0 = blockIdx.y * 128, col0 = blockIdx.x * 128;

    if (wid == 0) {
        TC_ALLOC(sb + 0, 128);
        TC_RELINQ();
    }
    if (tid == 0) MBAR_INIT(sb + 8, 1);

    // loads with 256 threads: 1024 uint4 slots, 4 tiles each
#pragma unroll
    for (int it = 0; it < 4; it++) {
        int idx = it * 256 + tid;   // 0..1023
        int r = idx >> 3;
        int c = idx & 7;
        uint32_t sw = swz128((uint32_t)(r * 128 + c * 16));
        *(uint4*)(smem + TSM_AH + sw) = *((const uint4*)(g_zhi + (size_t)(row0 + r) * ZC) + c);
        *(uint4*)(smem + TSM_AL + sw) = *((const uint4*)(g_zlo + (size_t)(row0 + r) * ZC) + c);
        *(uint4*)(smem + TSM_BH + sw) = *((const uint4*)(g_zhi + (size_t)(col0 + r) * ZC) + c);
        *(uint4*)(smem + TSM_BL + sw) = *((const uint4*)(g_zlo + (size_t)(col0 + r) * ZC) + c);
    }
    FENCE_PROXY_ASYNC();
    __syncthreads();

    uint32_t tmem;
    asm volatile("ld.shared.b32 %0, [%1];" : "=r"(tmem) : "r"(sb + 0));

    if (wid == 0 && elect1()) {
        uint64_t dAh = mk_desc(sb + TSM_AH);
        uint64_t dAl = mk_desc(sb + TSM_AL);
        uint64_t dBh = mk_desc(sb + TSM_BH);
        uint64_t dBl = mk_desc(sb + TSM_BL);
        bool first = true;
#pragma unroll
        for (int p = 0; p < 3; p++) {
            uint64_t da = (p == 2) ? dAl : dAh;
            uint64_t db = (p == 1) ? dBl : dBh;
#pragma unroll
            for (int k = 0; k < 4; k++) {
                mma_f16_ss(tmem, da + k * 2, db + k * 2, TC_IDESC, !first);
                first = false;
            }
        }
        TC_COMMIT(sb + 8);
    }

    MBAR_WAIT(sb + 8, 0);
    TC_FENCE_AFTER();

    // 8-warp epilogue: subpartition = wid & 3; warps 0-3 take chunks 0,1; warps 4-7 chunks 2,3
    int sp = wid & 3;
    int r = row0 + sp * 32 + lid;
    int ch0 = (wid >> 2) * 2;
#pragma unroll
    for (int cc = 0; cc < 2; cc++) {
        int ch = ch0 + cc;
        uint32_t dr[32];
        TC_LD_X32(dr, tmem + ch * 32);
        TC_WAIT_LD();
        if (r < NN) {
            int cbase = col0 + ch * 32;
            float v[32];
#pragma unroll
            for (int j = 0; j < 32; j++)
                v[j] = 1.f / (1.f + __expf(-__uint_as_float(dr[j])));
            float* orow = adj + (size_t)r * NN + cbase;
            if (cbase + 31 < NN) {
#pragma unroll
                for (int q = 0; q < 8; q++)
                    *(float4*)(orow + q * 4) =
                        make_float4(v[q * 4], v[q * 4 + 1], v[q * 4 + 2], v[q * 4 + 3]);
            } else {
#pragma unroll
                for (int j = 0; j < 32; j++)
                    if (cbase + j < NN) orow[j] = v[j];
            }
        }
    }
    TC_FENCE_BEFORE();
    __syncthreads();
    if (tid == 0) MBAR_INVAL(sb + 8);
    __syncthreads();
    if (wid == 0) TC_DEALLOC(tmem, 128);
#endif  // HAS_TCGEN05
}

// ---------------- launcher ----------------
extern "C" void kernel_launch(void* const* d_in, const int* in_sizes, int n_in,
                              void* d_out, int out_size) {
    const float* features = (const float*)d_in[0];
    const int*   src      = (const int*)d_in[1];
    const int*   dst      = (const int*)d_in[2];
    const float* noise    = (const float*)d_in[3];
    const float* W0  = (const float*)d_in[4];
    const float* al0 = (const float*)d_in[5];
    const float* ar0 = (const float*)d_in[6];
    const float* b0  = (const float*)d_in[7];
    const float* W1  = (const float*)d_in[8];
    const float* al1 = (const float*)d_in[9];
    const float* ar1 = (const float*)d_in[10];
    const float* b1  = (const float*)d_in[11];
    const float* W2  = (const float*)d_in[12];
    const float* al2 = (const float*)d_in[13];
    const float* ar2 = (const float*)d_in[14];
    const float* b2  = (const float*)d_in[15];

    float* out = (float*)d_out;
    float* z_out = out;
    float* adj_out = out + (size_t)NN * ZC;

    void* p;
    cudaGetSymbolAddress(&p, g_lin0); float* lin0 = (float*)p;
    cudaGetSymbolAddress(&p, g_gat0); float* gat0 = (float*)p;
    cudaGetSymbolAddress(&p, g_lin1); float* lin1 = (float*)p;
    cudaGetSymbolAddress(&p, g_lin2); float* lin2 = (float*)p;
    cudaGetSymbolAddress(&p, g_mean); float* meanp = (float*)p;
    cudaGetSymbolAddress(&p, g_lstd); float* lstdp = (float*)p;
    cudaGetSymbolAddress(&p, g_el);  float* el = (float*)p;
    cudaGetSymbolAddress(&p, g_er);  float* er = (float*)p;
    cudaGetSymbolAddress(&p, g_el2); float* el2 = (float*)p;
    cudaGetSymbolAddress(&p, g_er2); float* er2 = (float*)p;

    // edge sort by dst (shared by all 3 GAT layers)
    k_zero_deg<<<(NN + 255) / 256, 256>>>();
    k_hist<<<(NE + 255) / 256, 256>>>(dst);
    k_scan<<<1, 1024>>>();
    k_scatter<<<(NE + 255) / 256, 256>>>(src, dst);

    // ---- layer 0: 512 -> 256, relu (tcgen05 GEMM + fused el/er epilogue) ----
    k_splitx<<<(NPAD * FIN + 255) / 256, 256>>>(features);
    k_w0t<<<(HIDC * FIN + 255) / 256, 256>>>(W0);
    cudaFuncSetAttribute(k_lin0_tc, cudaFuncAttributeMaxDynamicSharedMemorySize, L_SMEM);
    k_lin0_tc<<<NPAD / 128, 128, L_SMEM>>>(lin0, al0, ar0);
    k_gat_fused4<<<NN, 64>>>(lin0, el, er, b0, gat0);

    // ---- layers 1 & 2: 256 -> 64 (dual-output + fused el/er) ----
    k_sgemm2<<<dim3(ZC / 64, (NN + 63) / 64, 2), 256>>>(
        gat0, W1, W2, lin1, lin2, al1, ar1, al2, ar2, el, er, el2, er2, NN, HIDC, ZC);
    k_gat_fused<ND1, false><<<NN, ZC>>>(lin1, el, er, b1, meanp);
    k_gat_fused<ND1, false><<<NN, ZC>>>(lin2, el2, er2, b2, lstdp);

    // ---- z + bf16 hi/lo split (fused, padded) ----
    k_z_split<<<(NPAD * ZC + 255) / 256, 256>>>(noise, z_out);

    // ---- adj = sigmoid(z @ z^T) via tcgen05 (256 threads, split epilogue) ----
    cudaFuncSetAttribute(k_adj_tc, cudaFuncAttributeMaxDynamicSharedMemorySize, TC_SMEM);
    k_adj_tc<<<dim3(NPAD / 128, NPAD / 128), 256, TC_SMEM>>>(adj_out);
}